// round 11
// baseline (speedup 1.0000x reference)
#include <cuda_runtime.h>
#include <cuda_fp16.h>
#include <cstdint>
#include <math.h>

#define BBx   8
#define SSx   512
#define DDx   2048
#define HHx   16
#define DWN   512
#define UPx   2048
#define RRx   512
#define VHDx  128
#define MROWS (BBx*SSx)
#define ZBx   (BBx*HHx)
#define QKD   (VHDx+RRx)
#define NDOWN (DWN*3)
#define NQ    (UPx + RRx*HHx)     // 10240  (qc | qr)
#define NKV   (UPx + UPx)         // 4096   (kc | vc)
#define INV_SCALE 0.0294627825494394758f

// A-side tensors: fp16 hi+lo planes (exact). B-side tensors: single fp16 plane.
__device__ uint16_t g_xsh [(size_t)MROWS*DDx];
__device__ uint16_t g_xsl [(size_t)MROWS*DDx];
__device__ uint16_t g_wdth[(size_t)NDOWN*DDx];      // B
__device__ float    g_bd  [NDOWN];
__device__ uint16_t g_wqth[(size_t)NQ*DWN];         // B
__device__ uint16_t g_wkvth[(size_t)NKV*DWN];       // B
__device__ float    g_bq  [NQ];
__device__ float    g_bkv [NKV];
__device__ uint16_t g_wfcth[(size_t)DDx*DDx];       // B
__device__ uint16_t g_d0sh[(size_t)MROWS*NDOWN];
__device__ uint16_t g_d0sl[(size_t)MROWS*NDOWN];
__device__ uint16_t g_quh [(size_t)MROWS*NQ];
__device__ uint16_t g_qul [(size_t)MROWS*NQ];
__device__ uint16_t g_kch [(size_t)MROWS*UPx];
__device__ float    g_vf  [(size_t)MROWS*UPx];
__device__ uint16_t g_krh [(size_t)MROWS*RRx];
__device__ float    g_sc  [(size_t)ZBx*SSx*SSx];
__device__ uint16_t g_psh [(size_t)ZBx*SSx*SSx];
__device__ uint16_t g_psl [(size_t)ZBx*SSx*SSx];
__device__ uint16_t g_vtsh[(size_t)ZBx*VHDx*SSx];   // B
__device__ uint16_t g_ofsh[(size_t)MROWS*UPx];
__device__ uint16_t g_ofsl[(size_t)MROWS*UPx];
__device__ float    g_sin [SSx*(RRx/2)];
__device__ float    g_cos [SSx*(RRx/2)];

__device__ __forceinline__ uint32_t smem_u32(const void* p) {
    uint32_t a;
    asm("{ .reg .u64 t; cvta.to.shared.u64 t, %1; cvt.u32.u64 %0, t; }" : "=r"(a) : "l"(p));
    return a;
}
__device__ __forceinline__ void split1(float v, uint16_t& h, uint16_t& l) {
    __half hb = __float2half_rn(v);
    __half lb = __float2half_rn(v - __half2float(hb));
    h = __half_as_ushort(hb); l = __half_as_ushort(lb);
}
__device__ __forceinline__ uint2 split2(float a, float b) {
    uint16_t ah, al, bh, bl; split1(a, ah, al); split1(b, bh, bl);
    return make_uint2((uint32_t)ah | ((uint32_t)bh << 16),
                      (uint32_t)al | ((uint32_t)bl << 16));
}
__device__ __forceinline__ uint32_t h2pack(float a, float b) {
    __half2 h = __floats2half2_rn(a, b);
    return *(uint32_t*)&h;
}
__device__ __forceinline__ float join1(uint16_t h, uint16_t l) {
    return __half2float(__ushort_as_half(h)) + __half2float(__ushort_as_half(l));
}
__device__ __forceinline__ void ldm4(uint32_t* r, uint32_t addr) {
    asm volatile("ldmatrix.sync.aligned.m8n8.x4.shared.b16 {%0,%1,%2,%3}, [%4];"
        : "=r"(r[0]), "=r"(r[1]), "=r"(r[2]), "=r"(r[3]) : "r"(addr));
}
__device__ __forceinline__ void mma16816(float* c, const uint32_t* a, const uint32_t* b) {
    asm volatile("mma.sync.aligned.m16n8k16.row.col.f32.f16.f16.f32 "
        "{%0,%1,%2,%3}, {%4,%5,%6,%7}, {%8,%9}, {%0,%1,%2,%3};"
        : "+f"(c[0]), "+f"(c[1]), "+f"(c[2]), "+f"(c[3])
        : "r"(a[0]), "r"(a[1]), "r"(a[2]), "r"(a[3]), "r"(b[0]), "r"(b[1]));
}
#define CP16(dst, src) \
    asm volatile("cp.async.cg.shared.global [%0], [%1], 16;" :: "r"(dst), "l"(src))
#define CP_COMMIT() asm volatile("cp.async.commit_group;" ::: "memory")
#define CP_WAIT1()  asm volatile("cp.async.wait_group 1;" ::: "memory")

#define PITCH  80
#define PLA_L  (128*PITCH)
#define STG_L  (3*PLA_L)          // 30720 per stage
#define STAGES 3
#define SMEMB  (STAGES*STG_L)     // 92160/CTA -> 2 CTAs/SM (184KB < 228KB)

// ------------------ generic GEMM: C = scale*(A @ B^T) + bias --------------------
// emode 0: std; emode 1: q-up rope+split; emode 2: kv-up (K fp16 / V fp32)
__global__ void __launch_bounds__(256, 2) k_gemm(
    const uint16_t* __restrict__ Ah, const uint16_t* __restrict__ Al, int lda, long long aB,
    const uint16_t* __restrict__ Bh, int ldb, long long bB,
    float* Cf, uint16_t* Csh, uint16_t* Csl, int ldc, long long cO, long long cI,
    const float* __restrict__ bias, float scale, int K, int emode)
{
    extern __shared__ __align__(16) char smem[];
    const uint32_t sb = smem_u32(smem);
    const int tid = threadIdx.x, lane = tid & 31, wid = tid >> 5;
    const int wm = wid >> 1, wn = wid & 1;     // 4m x 2n
    const int z = blockIdx.z, bm = blockIdx.y, bn = blockIdx.x;

    const uint16_t* pb0 = Ah + (size_t)z * aB + (size_t)bm * 128 * lda;
    const uint16_t* pb1 = Al + (size_t)z * aB + (size_t)bm * 128 * lda;
    const uint16_t* pb2 = Bh + (size_t)z * bB + (size_t)bn * 128 * ldb;
    const int nCh = K / 32;

    auto issue = [&](int c) {
        if (c < nCh) {
            const int kc = c * 32;
            const uint32_t sdst = sb + (c % STAGES) * STG_L;
            const int row = (tid >> 2);
            const int col16 = (tid & 3);
            #pragma unroll
            for (int p = 0; p < 6; p++) {
                const int pl = p >> 1;
                const int r = (p & 1) * 64 + row;
                const uint16_t* src = (pl == 0 ? pb0 : pl == 1 ? pb1 : pb2);
                const int ld = (pl < 2) ? lda : ldb;
                CP16(sdst + pl * PLA_L + r * PITCH + col16 * 16,
                     src + (size_t)r * ld + kc + col16 * 8);
            }
        }
        CP_COMMIT();   // empty groups at tail keep wait_group semantics exact
    };

    float acc[2][8][4];
    #pragma unroll
    for (int i = 0; i < 2; i++)
        #pragma unroll
        for (int j = 0; j < 8; j++)
            #pragma unroll
            for (int r = 0; r < 4; r++) acc[i][j][r] = 0.f;

    issue(0); issue(1);

    for (int c = 0; c < nCh; c++) {
        CP_WAIT1();                 // copy(c) resident; copy(c+1) may be in flight
        __syncthreads();            // publishes copy(c); proves compute(c-1) done
        issue(c + 2);               // refill buf (c-1)%3; overlaps compute(c)

        const uint32_t sbuf = sb + (c % STAGES) * STG_L;
        #pragma unroll
        for (int k16 = 0; k16 < 2; k16++) {
            uint32_t af[2][2][4];
            uint32_t abase = sbuf + (wm * 32 + (lane & 15)) * PITCH
                           + (k16 * 16 + (lane >> 4) * 8) * 2;
            #pragma unroll
            for (int mt = 0; mt < 2; mt++) {
                ldm4(af[0][mt], abase + mt * 16 * PITCH);
                ldm4(af[1][mt], abase + PLA_L + mt * 16 * PITCH);
            }
            uint32_t bbase = sbuf + 2 * PLA_L
                + (wn * 64 + (lane & 7) + ((lane >> 4) << 3)) * PITCH
                + (k16 * 16 + ((lane >> 3) & 1) * 8) * 2;
            #pragma unroll
            for (int nb = 0; nb < 4; nb++) {
                uint32_t bh[4];
                ldm4(bh, bbase + nb * 16 * PITCH);
                #pragma unroll
                for (int hf = 0; hf < 2; hf++) {
                    const int nt = nb * 2 + hf;
                    #pragma unroll
                    for (int mt = 0; mt < 2; mt++) {
                        mma16816(acc[mt][nt], af[0][mt], &bh[2 * hf]);
                        mma16816(acc[mt][nt], af[1][mt], &bh[2 * hf]);
                    }
                }
            }
        }
    }

    const long long coff = (long long)(z >> 4) * cO + (long long)(z & 15) * cI;
    #pragma unroll
    for (int nt = 0; nt < 8; nt++) {
        const int gc = bn * 128 + wn * 64 + nt * 8 + (lane & 3) * 2;
        float2 bv = make_float2(0.f, 0.f);
        if (bias) bv = *(const float2*)(bias + gc);
        #pragma unroll
        for (int mt = 0; mt < 2; mt++) {
            const int r0 = bm * 128 + wm * 32 + mt * 16 + (lane >> 2);
            #pragma unroll
            for (int half = 0; half < 2; half++) {
                const int grow = r0 + half * 8;
                float v0 = acc[mt][nt][2 * half + 0] * scale + bv.x;
                float v1 = acc[mt][nt][2 * half + 1] * scale + bv.y;
                if (emode == 0) {
                    const long long gp = coff + (long long)grow * ldc + gc;
                    if (Cf) *(float2*)(Cf + gp) = make_float2(v0, v1);
                    if (Csh) {
                        uint2 s = split2(v0, v1);
                        *(uint32_t*)(Csh + gp) = s.x;
                        *(uint32_t*)(Csl + gp) = s.y;
                    }
                } else if (emode == 1) {
                    if (gc >= 2048) {
                        const int s = grow & (SSx - 1);
                        const int i2 = (gc - 2048) & (RRx - 1);
                        const int ii = s * 256 + (i2 >> 1);
                        float sn = g_sin[ii], cs = g_cos[ii];
                        float o0 = v0 * cs - v1 * sn;
                        float o1 = v1 * cs + v0 * sn;
                        v0 = o0; v1 = o1;
                    }
                    const long long gp = (long long)grow * ldc + gc;
                    uint2 s = split2(v0, v1);
                    *(uint32_t*)(Csh + gp) = s.x;
                    *(uint32_t*)(Csl + gp) = s.y;
                } else {   // emode == 2
                    if (gc < 2048)
                        *(uint32_t*)(Csh + (long long)grow * 2048 + gc) = h2pack(v0, v1);
                    else
                        *(float2*)(Cf + (long long)grow * 2048 + gc - 2048) =
                            make_float2(v0, v1);
                }
            }
        }
    }
}

// ------------------ scores GEMM with piecewise q/k addressing -------------------
__global__ void __launch_bounds__(256, 2) k_gemm_qk()
{
    extern __shared__ __align__(16) char smem[];
    const uint32_t sb = smem_u32(smem);
    const int tid = threadIdx.x, lane = tid & 31, wid = tid >> 5;
    const int wm = wid >> 1, wn = wid & 1;
    const int z = blockIdx.z, bm = blockIdx.y, bn = blockIdx.x;
    const int b = z >> 4, h = z & 15;
    const long long gRow0 = (long long)b * SSx + bm * 128;
    const long long kRow0 = (long long)b * SSx + bn * 128;
    const int nCh = QKD / 32;    // 20

    auto issue = [&](int c) {
        if (c < nCh) {
            const uint32_t sdst = sb + (c % STAGES) * STG_L;
            const int row = (tid >> 2);
            const int col16 = (tid & 3);
            const int colA = (c < 4) ? (h * VHDx + c * 32)
                                     : (2048 + h * RRx + (c - 4) * 32);
            #pragma unroll
            for (int p = 0; p < 6; p++) {
                const int pl = p >> 1;
                const int r = (p & 1) * 64 + row;
                uint32_t dst = sdst + pl * PLA_L + r * PITCH + col16 * 16;
                if (pl == 0) {
                    CP16(dst, g_quh + (gRow0 + r) * NQ + colA + col16 * 8);
                } else if (pl == 1) {
                    CP16(dst, g_qul + (gRow0 + r) * NQ + colA + col16 * 8);
                } else {
                    if (c < 4)
                        CP16(dst, g_kch + (kRow0 + r) * UPx + h * VHDx + c * 32 + col16 * 8);
                    else
                        CP16(dst, g_krh + (kRow0 + r) * RRx + (c - 4) * 32 + col16 * 8);
                }
            }
        }
        CP_COMMIT();
    };

    float acc[2][8][4];
    #pragma unroll
    for (int i = 0; i < 2; i++)
        #pragma unroll
        for (int j = 0; j < 8; j++)
            #pragma unroll
            for (int r = 0; r < 4; r++) acc[i][j][r] = 0.f;

    issue(0); issue(1);

    for (int c = 0; c < nCh; c++) {
        CP_WAIT1();
        __syncthreads();
        issue(c + 2);

        const uint32_t sbuf = sb + (c % STAGES) * STG_L;
        #pragma unroll
        for (int k16 = 0; k16 < 2; k16++) {
            uint32_t af[2][2][4];
            uint32_t abase = sbuf + (wm * 32 + (lane & 15)) * PITCH
                           + (k16 * 16 + (lane >> 4) * 8) * 2;
            #pragma unroll
            for (int mt = 0; mt < 2; mt++) {
                ldm4(af[0][mt], abase + mt * 16 * PITCH);
                ldm4(af[1][mt], abase + PLA_L + mt * 16 * PITCH);
            }
            uint32_t bbase = sbuf + 2 * PLA_L
                + (wn * 64 + (lane & 7) + ((lane >> 4) << 3)) * PITCH
                + (k16 * 16 + ((lane >> 3) & 1) * 8) * 2;
            #pragma unroll
            for (int nb = 0; nb < 4; nb++) {
                uint32_t bh[4];
                ldm4(bh, bbase + nb * 16 * PITCH);
                #pragma unroll
                for (int hf = 0; hf < 2; hf++) {
                    const int nt = nb * 2 + hf;
                    #pragma unroll
                    for (int mt = 0; mt < 2; mt++) {
                        mma16816(acc[mt][nt], af[0][mt], &bh[2 * hf]);
                        mma16816(acc[mt][nt], af[1][mt], &bh[2 * hf]);
                    }
                }
            }
        }
    }

    float* C = g_sc + (size_t)z * SSx * SSx;
    #pragma unroll
    for (int nt = 0; nt < 8; nt++) {
        const int gc = bn * 128 + wn * 64 + nt * 8 + (lane & 3) * 2;
        #pragma unroll
        for (int mt = 0; mt < 2; mt++) {
            const int r0 = bm * 128 + wm * 32 + mt * 16 + (lane >> 2);
            #pragma unroll
            for (int half = 0; half < 2; half++) {
                const long long gp = (long long)(r0 + half * 8) * SSx + gc;
                *(float2*)(C + gp) = make_float2(
                    acc[mt][nt][2 * half + 0] * INV_SCALE,
                    acc[mt][nt][2 * half + 1] * INV_SCALE);
            }
        }
    }
}

__global__ void k_split_x(const float* __restrict__ s, uint16_t* __restrict__ dh,
                          uint16_t* __restrict__ dl, int n2) {
    int i = blockIdx.x * 256 + threadIdx.x;
    if (i < n2) {
        float2 v = *(const float2*)(s + 2 * i);
        uint2 sp = split2(v.x, v.y);
        *(uint32_t*)(dh + 2 * i) = sp.x;
        *(uint32_t*)(dl + 2 * i) = sp.y;
    }
}
__global__ void k_trsp(const float* __restrict__ W, uint16_t* __restrict__ Wth,
                       int Kd, int Nd) {
    __shared__ float t[32][33];
    int n0 = blockIdx.x * 32, k0 = blockIdx.y * 32;
    int tx = threadIdx.x, ty = threadIdx.y;
    #pragma unroll
    for (int i = 0; i < 32; i += 8)
        t[ty + i][tx] = W[(size_t)(k0 + ty + i) * Nd + n0 + tx];
    __syncthreads();
    #pragma unroll
    for (int i = 0; i < 32; i += 8)
        Wth[(size_t)(n0 + ty + i) * Kd + k0 + tx] =
            __half_as_ushort(__float2half_rn(t[tx][ty + i]));
}
__global__ void k_cat3(float* dst, const float* a, const float* b, const float* c,
                       int na, int nb, int nc) {
    int i = blockIdx.x * 256 + threadIdx.x;
    if (i < na) dst[i] = a[i];
    else if (i < na + nb) dst[i] = b[i - na];
    else if (i < na + nb + nc) dst[i] = c[i - na - nb];
}
__global__ void k_cat2(float* dst, const float* a, const float* b, int na, int nb) {
    int i = blockIdx.x * 256 + threadIdx.x;
    if (i < na) dst[i] = a[i];
    else if (i < na + nb) dst[i] = b[i - na];
}
__global__ void k_table() {
    int idx = blockIdx.x * 256 + threadIdx.x;
    int s = idx >> 8, i = idx & 255;
    float dv = expf((float)(2 * i) * (-9.210340371976184f / (float)RRx));
    float sn, cs; sincosf((float)s * dv, &sn, &cs);
    g_sin[idx] = sn; g_cos[idx] = cs;
}
__global__ void k_rope_k() {
    int idx = blockIdx.x * 256 + threadIdx.x;
    int i = idx & 255, row = idx >> 8, s = row & (SSx - 1);
    size_t o = (size_t)row * NDOWN + 1024 + 2 * i;
    float vx = join1(g_d0sh[o],     g_d0sl[o]);
    float vy = join1(g_d0sh[o + 1], g_d0sl[o + 1]);
    float sn = g_sin[s * 256 + i], cs = g_cos[s * 256 + i];
    *(uint32_t*)(g_krh + (size_t)row * RRx + 2 * i) =
        h2pack(vx * cs - vy * sn, vy * cs + vx * sn);
}
__global__ void k_vt() {
    __shared__ float t[32][33];
    int z = blockIdx.z, b = z >> 4, h = z & 15;
    int s0 = blockIdx.x * 32, d0 = blockIdx.y * 32;
    int tx = threadIdx.x, ty = threadIdx.y;
    #pragma unroll
    for (int i = 0; i < 32; i += 8)
        t[ty + i][tx] = g_vf[(size_t)(b * SSx + s0 + ty + i) * UPx + h * VHDx + d0 + tx];
    __syncthreads();
    #pragma unroll
    for (int i = 0; i < 32; i += 8)
        g_vtsh[(size_t)z * (VHDx * SSx) + (size_t)(d0 + ty + i) * SSx + s0 + tx] =
            __half_as_ushort(__float2half_rn(t[tx][ty + i]));
}
__global__ void __launch_bounds__(128) k_softmax() {
    size_t row = blockIdx.x;
    const float* p = g_sc + row * SSx;
    int t = threadIdx.x;
    float4 v = ((const float4*)p)[t];
    float m = fmaxf(fmaxf(v.x, v.y), fmaxf(v.z, v.w));
    #pragma unroll
    for (int o = 16; o; o >>= 1) m = fmaxf(m, __shfl_xor_sync(0xffffffffu, m, o));
    __shared__ float rm[4], rs[4];
    if ((t & 31) == 0) rm[t >> 5] = m;
    __syncthreads();
    m = fmaxf(fmaxf(rm[0], rm[1]), fmaxf(rm[2], rm[3]));
    v.x = __expf(v.x - m); v.y = __expf(v.y - m);
    v.z = __expf(v.z - m); v.w = __expf(v.w - m);
    float s = v.x + v.y + v.z + v.w;
    #pragma unroll
    for (int o = 16; o; o >>= 1) s += __shfl_xor_sync(0xffffffffu, s, o);
    if ((t & 31) == 0) rs[t >> 5] = s;
    __syncthreads();
    s = rs[0] + rs[1] + rs[2] + rs[3];
    float inv = 1.f / s;
    uint2 s01 = split2(v.x * inv, v.y * inv);
    uint2 s23 = split2(v.z * inv, v.w * inv);
    *(uint2*)(g_psh + row * SSx + t * 4) = make_uint2(s01.x, s23.x);
    *(uint2*)(g_psl + row * SSx + t * 4) = make_uint2(s01.y, s23.y);
}

extern "C" void kernel_launch(void* const* d_in, const int* in_sizes, int n_in,
                              void* d_out, int out_size)
{
    const float* X    = (const float*)d_in[0];
    const float* Wdq  = (const float*)d_in[1];
    const float* bdq  = (const float*)d_in[2];
    const float* Wdkv = (const float*)d_in[3];
    const float* bdkv = (const float*)d_in[4];
    const float* Wuq  = (const float*)d_in[5];
    const float* buq  = (const float*)d_in[6];
    const float* Wuk  = (const float*)d_in[7];
    const float* buk  = (const float*)d_in[8];
    const float* Wuv  = (const float*)d_in[9];
    const float* buv  = (const float*)d_in[10];
    const float* Wqr  = (const float*)d_in[11];
    const float* bqr  = (const float*)d_in[12];
    const float* Wkr  = (const float*)d_in[13];
    const float* bkr  = (const float*)d_in[14];
    const float* Wfc  = (const float*)d_in[15];
    const float* bfc  = (const float*)d_in[16];
    float* out = (float*)d_out;

    cudaFuncSetAttribute(k_gemm, cudaFuncAttributeMaxDynamicSharedMemorySize, SMEMB);
    cudaFuncSetAttribute(k_gemm_qk, cudaFuncAttributeMaxDynamicSharedMemorySize, SMEMB);

    #define SYM(v, g) void* v; cudaGetSymbolAddress(&v, g)
    SYM(p_xsh, g_xsh);   SYM(p_xsl, g_xsl);
    SYM(p_wdth, g_wdth); SYM(p_bd, g_bd);
    SYM(p_wqth, g_wqth); SYM(p_wkvth, g_wkvth);
    SYM(p_bq, g_bq); SYM(p_bkv, g_bkv);
    SYM(p_wfcth, g_wfcth);
    SYM(p_d0sh, g_d0sh); SYM(p_d0sl, g_d0sl);
    SYM(p_quh, g_quh); SYM(p_qul, g_qul);
    SYM(p_kch, g_kch); SYM(p_vf, g_vf);
    SYM(p_sc, g_sc); SYM(p_psh, g_psh); SYM(p_psl, g_psl);
    SYM(p_vtsh, g_vtsh);
    SYM(p_ofsh, g_ofsh); SYM(p_ofsl, g_ofsl);
    #undef SYM

    dim3 tb(32, 8);
    k_table<<<SSx, 256>>>();
    k_split_x<<<(MROWS * DDx / 2) / 256, 256>>>(X, (uint16_t*)p_xsh, (uint16_t*)p_xsl,
                                                MROWS * DDx / 2);
    k_trsp<<<dim3(16, 64), tb>>>(Wdq,  (uint16_t*)p_wdth, 2048, 512);
    k_trsp<<<dim3(16, 64), tb>>>(Wdkv, (uint16_t*)p_wdth + (size_t)512 * 2048, 2048, 512);
    k_trsp<<<dim3(16, 64), tb>>>(Wkr,  (uint16_t*)p_wdth + (size_t)1024 * 2048, 2048, 512);
    k_trsp<<<dim3(64, 16), tb>>>(Wuq, (uint16_t*)p_wqth, 512, 2048);
    k_trsp<<<dim3(256, 16), tb>>>(Wqr, (uint16_t*)p_wqth + (size_t)UPx * 512, 512, 8192);
    k_trsp<<<dim3(64, 16), tb>>>(Wuk, (uint16_t*)p_wkvth, 512, 2048);
    k_trsp<<<dim3(64, 16), tb>>>(Wuv, (uint16_t*)p_wkvth + (size_t)UPx * 512, 512, 2048);
    k_trsp<<<dim3(64, 64), tb>>>(Wfc, (uint16_t*)p_wfcth, 2048, 2048);
    k_cat3<<<(NDOWN + 255) / 256, 256>>>((float*)p_bd, bdq, bdkv, bkr, 512, 512, 512);
    k_cat2<<<(NQ + 255) / 256, 256>>>((float*)p_bq, buq, bqr, UPx, RRx * HHx);
    k_cat2<<<(NKV + 255) / 256, 256>>>((float*)p_bkv, buk, buv, UPx, UPx);

    // fused down-proj: M=4096, N=1536, K=2048 (split output)
    k_gemm<<<dim3(12, 32, 1), 256, SMEMB>>>(
        (uint16_t*)p_xsh, (uint16_t*)p_xsl, DDx, 0,
        (uint16_t*)p_wdth, DDx, 0,
        nullptr, (uint16_t*)p_d0sh, (uint16_t*)p_d0sl, NDOWN, 0, 0,
        (float*)p_bd, 1.f, DDx, 0);

    // merged q-side up-proj with fused rope+split: M=4096, N=10240, K=512
    k_gemm<<<dim3(80, 32, 1), 256, SMEMB>>>(
        (uint16_t*)p_d0sh, (uint16_t*)p_d0sl, NDOWN, 0,
        (uint16_t*)p_wqth, DWN, 0,
        nullptr, (uint16_t*)p_quh, (uint16_t*)p_qul, NQ, 0, 0,
        (float*)p_bq, 1.f, DWN, 1);
    // merged kv-side up-proj: K content fp16 + V fp32: M=4096, N=4096, K=512
    k_gemm<<<dim3(32, 32, 1), 256, SMEMB>>>(
        (uint16_t*)p_d0sh + 512, (uint16_t*)p_d0sl + 512, NDOWN, 0,
        (uint16_t*)p_wkvth, DWN, 0,
        (float*)p_vf, (uint16_t*)p_kch, nullptr, 2048, 0, 0,
        (float*)p_bkv, 1.f, DWN, 2);

    k_rope_k<<<MROWS, 256>>>();
    k_vt<<<dim3(16, 4, ZBx), tb>>>();

    // scores: per z M=512, N=512, K=640, piecewise q/k sources
    k_gemm_qk<<<dim3(4, 4, ZBx), 256, SMEMB>>>();

    k_softmax<<<ZBx * SSx, 128>>>();

    // PV: per z M=512, N=128, K=512 -> split store scattered to [b,s,h*128+d]
    k_gemm<<<dim3(1, 4, ZBx), 256, SMEMB>>>(
        (uint16_t*)p_psh, (uint16_t*)p_psl, SSx, (long long)SSx * SSx,
        (uint16_t*)p_vtsh, SSx, (long long)VHDx * SSx,
        nullptr, (uint16_t*)p_ofsh, (uint16_t*)p_ofsl, UPx,
        (long long)SSx * UPx, (long long)VHDx,
        nullptr, 1.f, SSx, 0);

    // final: M=4096, N=2048, K=2048 -> out fp32
    k_gemm<<<dim3(16, 32, 1), 256, SMEMB>>>(
        (uint16_t*)p_ofsh, (uint16_t*)p_ofsl, UPx, 0,
        (uint16_t*)p_wfcth, DDx, 0,
        out, nullptr, nullptr, DDx, 0, 0, bfc, 1.f, DDx, 0);
}

// round 12
// speedup vs baseline: 1.0367x; 1.0367x over previous
#include <cuda_runtime.h>
#include <cuda_fp16.h>
#include <cstdint>
#include <math.h>

#define BBx   8
#define SSx   512
#define DDx   2048
#define HHx   16
#define DWN   512
#define UPx   2048
#define RRx   512
#define VHDx  128
#define MROWS (BBx*SSx)
#define ZBx   (BBx*HHx)
#define QKD   (VHDx+RRx)
#define NDOWN (DWN*3)
#define NQ    (UPx + RRx*HHx)     // 10240  (qc | qr)
#define NKV   (UPx + UPx)         // 4096   (kc | vc)
#define INV_SCALE 0.0294627825494394758f

// A-side tensors: fp16 hi+lo planes (exact). B-side tensors: single fp16 plane.
__device__ uint16_t g_xsh [(size_t)MROWS*DDx];
__device__ uint16_t g_xsl [(size_t)MROWS*DDx];
__device__ uint16_t g_wdth[(size_t)NDOWN*DDx];      // B
__device__ float    g_bd  [NDOWN];
__device__ uint16_t g_wqth[(size_t)NQ*DWN];         // B
__device__ uint16_t g_wkvth[(size_t)NKV*DWN];       // B
__device__ float    g_bq  [NQ];
__device__ float    g_bkv [NKV];
__device__ uint16_t g_wfcth[(size_t)DDx*DDx];       // B
__device__ uint16_t g_d0sh[(size_t)MROWS*NDOWN];
__device__ uint16_t g_d0sl[(size_t)MROWS*NDOWN];
__device__ uint16_t g_quh [(size_t)MROWS*NQ];
__device__ uint16_t g_qul [(size_t)MROWS*NQ];
__device__ uint16_t g_kch [(size_t)MROWS*UPx];
__device__ float    g_vf  [(size_t)MROWS*UPx];
__device__ uint16_t g_krh [(size_t)MROWS*RRx];
__device__ float    g_sc  [(size_t)ZBx*SSx*SSx];
__device__ uint16_t g_psh [(size_t)ZBx*SSx*SSx];    // probs: SINGLE fp16 plane
__device__ uint16_t g_vtsh[(size_t)ZBx*VHDx*SSx];   // B
__device__ uint16_t g_ofsh[(size_t)MROWS*UPx];
__device__ uint16_t g_ofsl[(size_t)MROWS*UPx];
__device__ float    g_sin [SSx*(RRx/2)];
__device__ float    g_cos [SSx*(RRx/2)];

__device__ __forceinline__ uint32_t smem_u32(const void* p) {
    uint32_t a;
    asm("{ .reg .u64 t; cvta.to.shared.u64 t, %1; cvt.u32.u64 %0, t; }" : "=r"(a) : "l"(p));
    return a;
}
__device__ __forceinline__ void split1(float v, uint16_t& h, uint16_t& l) {
    __half hb = __float2half_rn(v);
    __half lb = __float2half_rn(v - __half2float(hb));
    h = __half_as_ushort(hb); l = __half_as_ushort(lb);
}
__device__ __forceinline__ uint2 split2(float a, float b) {
    uint16_t ah, al, bh, bl; split1(a, ah, al); split1(b, bh, bl);
    return make_uint2((uint32_t)ah | ((uint32_t)bh << 16),
                      (uint32_t)al | ((uint32_t)bl << 16));
}
__device__ __forceinline__ uint32_t h2pack(float a, float b) {
    __half2 h = __floats2half2_rn(a, b);
    return *(uint32_t*)&h;
}
__device__ __forceinline__ float join1(uint16_t h, uint16_t l) {
    return __half2float(__ushort_as_half(h)) + __half2float(__ushort_as_half(l));
}
__device__ __forceinline__ void ldm4(uint32_t* r, uint32_t addr) {
    asm volatile("ldmatrix.sync.aligned.m8n8.x4.shared.b16 {%0,%1,%2,%3}, [%4];"
        : "=r"(r[0]), "=r"(r[1]), "=r"(r[2]), "=r"(r[3]) : "r"(addr));
}
__device__ __forceinline__ void mma16816(float* c, const uint32_t* a, const uint32_t* b) {
    asm volatile("mma.sync.aligned.m16n8k16.row.col.f32.f16.f16.f32 "
        "{%0,%1,%2,%3}, {%4,%5,%6,%7}, {%8,%9}, {%0,%1,%2,%3};"
        : "+f"(c[0]), "+f"(c[1]), "+f"(c[2]), "+f"(c[3])
        : "r"(a[0]), "r"(a[1]), "r"(a[2]), "r"(a[3]), "r"(b[0]), "r"(b[1]));
}
#define CP16(dst, src) \
    asm volatile("cp.async.cg.shared.global [%0], [%1], 16;" :: "r"(dst), "l"(src))
#define CP_COMMIT() asm volatile("cp.async.commit_group;" ::: "memory")
#define CP_WAIT0()  asm volatile("cp.async.wait_group 0;" ::: "memory")

#define PITCH  80
#define PLA_L  (128*PITCH)
#define STG_L  (3*PLA_L)          // 30720 per stage
#define SMEMB  (2*STG_L)          // 61440 -> 2 CTAs/SM

// ------------------ generic GEMM: C = scale*(A @ B^T) + bias --------------------
// emode 0: std; emode 1: q-up rope+split; emode 2: kv-up (K fp16 / V fp32)
// aSplit: 1 = A has hi+lo planes (2 mmas); 0 = A single plane (1 mma)
__global__ void __launch_bounds__(256, 2) k_gemm(
    const uint16_t* __restrict__ Ah, const uint16_t* __restrict__ Al, int lda, long long aB,
    const uint16_t* __restrict__ Bh, int ldb, long long bB,
    float* Cf, uint16_t* Csh, uint16_t* Csl, int ldc, long long cO, long long cI,
    const float* __restrict__ bias, float scale, int K, int emode, int aSplit)
{
    extern __shared__ __align__(16) char smem[];
    const uint32_t sb = smem_u32(smem);
    const int tid = threadIdx.x, lane = tid & 31, wid = tid >> 5;
    const int wm = wid >> 1, wn = wid & 1;     // 4m x 2n
    const int z = blockIdx.z, bm = blockIdx.y, bn = blockIdx.x;

    const uint16_t* pb0 = Ah + (size_t)z * aB + (size_t)bm * 128 * lda;
    const uint16_t* pb1 = Al + (size_t)z * aB + (size_t)bm * 128 * lda;
    const uint16_t* pb2 = Bh + (size_t)z * bB + (size_t)bn * 128 * ldb;
    const int nCh = K / 32;

    auto issue = [&](int c) {
        if (c < nCh) {
            const int kc = c * 32;
            const uint32_t sdst = sb + (c & 1) * STG_L;
            const int row = (tid >> 2);
            const int col16 = (tid & 3);
            #pragma unroll
            for (int p = 0; p < 6; p++) {
                const int pl = p >> 1;
                if (pl == 1 && !aSplit) continue;
                const int r = (p & 1) * 64 + row;
                const uint16_t* src = (pl == 0 ? pb0 : pl == 1 ? pb1 : pb2);
                const int ld = (pl < 2) ? lda : ldb;
                CP16(sdst + pl * PLA_L + r * PITCH + col16 * 16,
                     src + (size_t)r * ld + kc + col16 * 8);
            }
            CP_COMMIT();
        }
    };

    float acc[2][8][4];
    #pragma unroll
    for (int i = 0; i < 2; i++)
        #pragma unroll
        for (int j = 0; j < 8; j++)
            #pragma unroll
            for (int r = 0; r < 4; r++) acc[i][j][r] = 0.f;

    issue(0);

    for (int c = 0; c < nCh; c++) {
        CP_WAIT0();
        __syncthreads();
        issue(c + 1);

        const uint32_t sbuf = sb + (c & 1) * STG_L;
        #pragma unroll
        for (int k16 = 0; k16 < 2; k16++) {
            uint32_t af[2][2][4];
            uint32_t abase = sbuf + (wm * 32 + (lane & 15)) * PITCH
                           + (k16 * 16 + (lane >> 4) * 8) * 2;
            #pragma unroll
            for (int mt = 0; mt < 2; mt++) {
                ldm4(af[0][mt], abase + mt * 16 * PITCH);
                if (aSplit) ldm4(af[1][mt], abase + PLA_L + mt * 16 * PITCH);
            }
            uint32_t bbase = sbuf + 2 * PLA_L
                + (wn * 64 + (lane & 7) + ((lane >> 4) << 3)) * PITCH
                + (k16 * 16 + ((lane >> 3) & 1) * 8) * 2;
            #pragma unroll
            for (int nb = 0; nb < 4; nb++) {
                uint32_t bh[4];
                ldm4(bh, bbase + nb * 16 * PITCH);
                #pragma unroll
                for (int hf = 0; hf < 2; hf++) {
                    const int nt = nb * 2 + hf;
                    #pragma unroll
                    for (int mt = 0; mt < 2; mt++) {
                        mma16816(acc[mt][nt], af[0][mt], &bh[2 * hf]);
                        if (aSplit) mma16816(acc[mt][nt], af[1][mt], &bh[2 * hf]);
                    }
                }
            }
        }
    }

    const long long coff = (long long)(z >> 4) * cO + (long long)(z & 15) * cI;
    #pragma unroll
    for (int nt = 0; nt < 8; nt++) {
        const int gc = bn * 128 + wn * 64 + nt * 8 + (lane & 3) * 2;
        float2 bv = make_float2(0.f, 0.f);
        if (bias) bv = *(const float2*)(bias + gc);
        #pragma unroll
        for (int mt = 0; mt < 2; mt++) {
            const int r0 = bm * 128 + wm * 32 + mt * 16 + (lane >> 2);
            #pragma unroll
            for (int half = 0; half < 2; half++) {
                const int grow = r0 + half * 8;
                float v0 = acc[mt][nt][2 * half + 0] * scale + bv.x;
                float v1 = acc[mt][nt][2 * half + 1] * scale + bv.y;
                if (emode == 0) {
                    const long long gp = coff + (long long)grow * ldc + gc;
                    if (Cf) *(float2*)(Cf + gp) = make_float2(v0, v1);
                    if (Csh) {
                        uint2 s = split2(v0, v1);
                        *(uint32_t*)(Csh + gp) = s.x;
                        *(uint32_t*)(Csl + gp) = s.y;
                    }
                } else if (emode == 1) {
                    if (gc >= 2048) {
                        const int s = grow & (SSx - 1);
                        const int i2 = (gc - 2048) & (RRx - 1);
                        const int ii = s * 256 + (i2 >> 1);
                        float sn = g_sin[ii], cs = g_cos[ii];
                        float o0 = v0 * cs - v1 * sn;
                        float o1 = v1 * cs + v0 * sn;
                        v0 = o0; v1 = o1;
                    }
                    const long long gp = (long long)grow * ldc + gc;
                    uint2 s = split2(v0, v1);
                    *(uint32_t*)(Csh + gp) = s.x;
                    *(uint32_t*)(Csl + gp) = s.y;
                } else {   // emode == 2
                    if (gc < 2048)
                        *(uint32_t*)(Csh + (long long)grow * 2048 + gc) = h2pack(v0, v1);
                    else
                        *(float2*)(Cf + (long long)grow * 2048 + gc - 2048) =
                            make_float2(v0, v1);
                }
            }
        }
    }
}

// ------------------ scores GEMM with piecewise q/k addressing -------------------
__global__ void __launch_bounds__(256, 2) k_gemm_qk()
{
    extern __shared__ __align__(16) char smem[];
    const uint32_t sb = smem_u32(smem);
    const int tid = threadIdx.x, lane = tid & 31, wid = tid >> 5;
    const int wm = wid >> 1, wn = wid & 1;
    const int z = blockIdx.z, bm = blockIdx.y, bn = blockIdx.x;
    const int b = z >> 4, h = z & 15;
    const long long gRow0 = (long long)b * SSx + bm * 128;
    const long long kRow0 = (long long)b * SSx + bn * 128;
    const int nCh = QKD / 32;    // 20

    auto issue = [&](int c) {
        if (c < nCh) {
            const uint32_t sdst = sb + (c & 1) * STG_L;
            const int row = (tid >> 2);
            const int col16 = (tid & 3);
            const int colA = (c < 4) ? (h * VHDx + c * 32)
                                     : (2048 + h * RRx + (c - 4) * 32);
            #pragma unroll
            for (int p = 0; p < 6; p++) {
                const int pl = p >> 1;
                const int r = (p & 1) * 64 + row;
                uint32_t dst = sdst + pl * PLA_L + r * PITCH + col16 * 16;
                if (pl == 0) {
                    CP16(dst, g_quh + (gRow0 + r) * NQ + colA + col16 * 8);
                } else if (pl == 1) {
                    CP16(dst, g_qul + (gRow0 + r) * NQ + colA + col16 * 8);
                } else {
                    if (c < 4)
                        CP16(dst, g_kch + (kRow0 + r) * UPx + h * VHDx + c * 32 + col16 * 8);
                    else
                        CP16(dst, g_krh + (kRow0 + r) * RRx + (c - 4) * 32 + col16 * 8);
                }
            }
            CP_COMMIT();
        }
    };

    float acc[2][8][4];
    #pragma unroll
    for (int i = 0; i < 2; i++)
        #pragma unroll
        for (int j = 0; j < 8; j++)
            #pragma unroll
            for (int r = 0; r < 4; r++) acc[i][j][r] = 0.f;

    issue(0);

    for (int c = 0; c < nCh; c++) {
        CP_WAIT0();
        __syncthreads();
        issue(c + 1);

        const uint32_t sbuf = sb + (c & 1) * STG_L;
        #pragma unroll
        for (int k16 = 0; k16 < 2; k16++) {
            uint32_t af[2][2][4];
            uint32_t abase = sbuf + (wm * 32 + (lane & 15)) * PITCH
                           + (k16 * 16 + (lane >> 4) * 8) * 2;
            #pragma unroll
            for (int mt = 0; mt < 2; mt++) {
                ldm4(af[0][mt], abase + mt * 16 * PITCH);
                ldm4(af[1][mt], abase + PLA_L + mt * 16 * PITCH);
            }
            uint32_t bbase = sbuf + 2 * PLA_L
                + (wn * 64 + (lane & 7) + ((lane >> 4) << 3)) * PITCH
                + (k16 * 16 + ((lane >> 3) & 1) * 8) * 2;
            #pragma unroll
            for (int nb = 0; nb < 4; nb++) {
                uint32_t bh[4];
                ldm4(bh, bbase + nb * 16 * PITCH);
                #pragma unroll
                for (int hf = 0; hf < 2; hf++) {
                    const int nt = nb * 2 + hf;
                    #pragma unroll
                    for (int mt = 0; mt < 2; mt++) {
                        mma16816(acc[mt][nt], af[0][mt], &bh[2 * hf]);
                        mma16816(acc[mt][nt], af[1][mt], &bh[2 * hf]);
                    }
                }
            }
        }
    }

    float* C = g_sc + (size_t)z * SSx * SSx;
    #pragma unroll
    for (int nt = 0; nt < 8; nt++) {
        const int gc = bn * 128 + wn * 64 + nt * 8 + (lane & 3) * 2;
        #pragma unroll
        for (int mt = 0; mt < 2; mt++) {
            const int r0 = bm * 128 + wm * 32 + mt * 16 + (lane >> 2);
            #pragma unroll
            for (int half = 0; half < 2; half++) {
                const long long gp = (long long)(r0 + half * 8) * SSx + gc;
                *(float2*)(C + gp) = make_float2(
                    acc[mt][nt][2 * half + 0] * INV_SCALE,
                    acc[mt][nt][2 * half + 1] * INV_SCALE);
            }
        }
    }
}

__global__ void k_split_x(const float* __restrict__ s, uint16_t* __restrict__ dh,
                          uint16_t* __restrict__ dl, int n2) {
    int i = blockIdx.x * 256 + threadIdx.x;
    if (i < n2) {
        float2 v = *(const float2*)(s + 2 * i);
        uint2 sp = split2(v.x, v.y);
        *(uint32_t*)(dh + 2 * i) = sp.x;
        *(uint32_t*)(dl + 2 * i) = sp.y;
    }
}
__global__ void k_trsp(const float* __restrict__ W, uint16_t* __restrict__ Wth,
                       int Kd, int Nd) {
    __shared__ float t[32][33];
    int n0 = blockIdx.x * 32, k0 = blockIdx.y * 32;
    int tx = threadIdx.x, ty = threadIdx.y;
    #pragma unroll
    for (int i = 0; i < 32; i += 8)
        t[ty + i][tx] = W[(size_t)(k0 + ty + i) * Nd + n0 + tx];
    __syncthreads();
    #pragma unroll
    for (int i = 0; i < 32; i += 8)
        Wth[(size_t)(n0 + ty + i) * Kd + k0 + tx] =
            __half_as_ushort(__float2half_rn(t[tx][ty + i]));
}
__global__ void k_cat3(float* dst, const float* a, const float* b, const float* c,
                       int na, int nb, int nc) {
    int i = blockIdx.x * 256 + threadIdx.x;
    if (i < na) dst[i] = a[i];
    else if (i < na + nb) dst[i] = b[i - na];
    else if (i < na + nb + nc) dst[i] = c[i - na - nb];
}
__global__ void k_cat2(float* dst, const float* a, const float* b, int na, int nb) {
    int i = blockIdx.x * 256 + threadIdx.x;
    if (i < na) dst[i] = a[i];
    else if (i < na + nb) dst[i] = b[i - na];
}
__global__ void k_table() {
    int idx = blockIdx.x * 256 + threadIdx.x;
    int s = idx >> 8, i = idx & 255;
    float dv = expf((float)(2 * i) * (-9.210340371976184f / (float)RRx));
    float sn, cs; sincosf((float)s * dv, &sn, &cs);
    g_sin[idx] = sn; g_cos[idx] = cs;
}
__global__ void k_rope_k() {
    int idx = blockIdx.x * 256 + threadIdx.x;
    int i = idx & 255, row = idx >> 8, s = row & (SSx - 1);
    size_t o = (size_t)row * NDOWN + 1024 + 2 * i;
    float vx = join1(g_d0sh[o],     g_d0sl[o]);
    float vy = join1(g_d0sh[o + 1], g_d0sl[o + 1]);
    float sn = g_sin[s * 256 + i], cs = g_cos[s * 256 + i];
    *(uint32_t*)(g_krh + (size_t)row * RRx + 2 * i) =
        h2pack(vx * cs - vy * sn, vy * cs + vx * sn);
}
__global__ void k_vt() {
    __shared__ float t[32][33];
    int z = blockIdx.z, b = z >> 4, h = z & 15;
    int s0 = blockIdx.x * 32, d0 = blockIdx.y * 32;
    int tx = threadIdx.x, ty = threadIdx.y;
    #pragma unroll
    for (int i = 0; i < 32; i += 8)
        t[ty + i][tx] = g_vf[(size_t)(b * SSx + s0 + ty + i) * UPx + h * VHDx + d0 + tx];
    __syncthreads();
    #pragma unroll
    for (int i = 0; i < 32; i += 8)
        g_vtsh[(size_t)z * (VHDx * SSx) + (size_t)(d0 + ty + i) * SSx + s0 + tx] =
            __half_as_ushort(__float2half_rn(t[tx][ty + i]));
}
__global__ void __launch_bounds__(128) k_softmax() {
    size_t row = blockIdx.x;
    const float* p = g_sc + row * SSx;
    int t = threadIdx.x;
    float4 v = ((const float4*)p)[t];
    float m = fmaxf(fmaxf(v.x, v.y), fmaxf(v.z, v.w));
    #pragma unroll
    for (int o = 16; o; o >>= 1) m = fmaxf(m, __shfl_xor_sync(0xffffffffu, m, o));
    __shared__ float rm[4], rs[4];
    if ((t & 31) == 0) rm[t >> 5] = m;
    __syncthreads();
    m = fmaxf(fmaxf(rm[0], rm[1]), fmaxf(rm[2], rm[3]));
    v.x = __expf(v.x - m); v.y = __expf(v.y - m);
    v.z = __expf(v.z - m); v.w = __expf(v.w - m);
    float s = v.x + v.y + v.z + v.w;
    #pragma unroll
    for (int o = 16; o; o >>= 1) s += __shfl_xor_sync(0xffffffffu, s, o);
    if ((t & 31) == 0) rs[t >> 5] = s;
    __syncthreads();
    s = rs[0] + rs[1] + rs[2] + rs[3];
    float inv = 1.f / s;
    *(uint2*)(g_psh + row * SSx + t * 4) =
        make_uint2(h2pack(v.x * inv, v.y * inv), h2pack(v.z * inv, v.w * inv));
}

extern "C" void kernel_launch(void* const* d_in, const int* in_sizes, int n_in,
                              void* d_out, int out_size)
{
    const float* X    = (const float*)d_in[0];
    const float* Wdq  = (const float*)d_in[1];
    const float* bdq  = (const float*)d_in[2];
    const float* Wdkv = (const float*)d_in[3];
    const float* bdkv = (const float*)d_in[4];
    const float* Wuq  = (const float*)d_in[5];
    const float* buq  = (const float*)d_in[6];
    const float* Wuk  = (const float*)d_in[7];
    const float* buk  = (const float*)d_in[8];
    const float* Wuv  = (const float*)d_in[9];
    const float* buv  = (const float*)d_in[10];
    const float* Wqr  = (const float*)d_in[11];
    const float* bqr  = (const float*)d_in[12];
    const float* Wkr  = (const float*)d_in[13];
    const float* bkr  = (const float*)d_in[14];
    const float* Wfc  = (const float*)d_in[15];
    const float* bfc  = (const float*)d_in[16];
    float* out = (float*)d_out;

    cudaFuncSetAttribute(k_gemm, cudaFuncAttributeMaxDynamicSharedMemorySize, SMEMB);
    cudaFuncSetAttribute(k_gemm_qk, cudaFuncAttributeMaxDynamicSharedMemorySize, SMEMB);

    #define SYM(v, g) void* v; cudaGetSymbolAddress(&v, g)
    SYM(p_xsh, g_xsh);   SYM(p_xsl, g_xsl);
    SYM(p_wdth, g_wdth); SYM(p_bd, g_bd);
    SYM(p_wqth, g_wqth); SYM(p_wkvth, g_wkvth);
    SYM(p_bq, g_bq); SYM(p_bkv, g_bkv);
    SYM(p_wfcth, g_wfcth);
    SYM(p_d0sh, g_d0sh); SYM(p_d0sl, g_d0sl);
    SYM(p_quh, g_quh); SYM(p_qul, g_qul);
    SYM(p_kch, g_kch); SYM(p_vf, g_vf);
    SYM(p_sc, g_sc); SYM(p_psh, g_psh);
    SYM(p_vtsh, g_vtsh);
    SYM(p_ofsh, g_ofsh); SYM(p_ofsl, g_ofsl);
    #undef SYM

    dim3 tb(32, 8);
    k_table<<<SSx, 256>>>();
    k_split_x<<<(MROWS * DDx / 2) / 256, 256>>>(X, (uint16_t*)p_xsh, (uint16_t*)p_xsl,
                                                MROWS * DDx / 2);
    k_trsp<<<dim3(16, 64), tb>>>(Wdq,  (uint16_t*)p_wdth, 2048, 512);
    k_trsp<<<dim3(16, 64), tb>>>(Wdkv, (uint16_t*)p_wdth + (size_t)512 * 2048, 2048, 512);
    k_trsp<<<dim3(16, 64), tb>>>(Wkr,  (uint16_t*)p_wdth + (size_t)1024 * 2048, 2048, 512);
    k_trsp<<<dim3(64, 16), tb>>>(Wuq, (uint16_t*)p_wqth, 512, 2048);
    k_trsp<<<dim3(256, 16), tb>>>(Wqr, (uint16_t*)p_wqth + (size_t)UPx * 512, 512, 8192);
    k_trsp<<<dim3(64, 16), tb>>>(Wuk, (uint16_t*)p_wkvth, 512, 2048);
    k_trsp<<<dim3(64, 16), tb>>>(Wuv, (uint16_t*)p_wkvth + (size_t)UPx * 512, 512, 2048);
    k_trsp<<<dim3(64, 64), tb>>>(Wfc, (uint16_t*)p_wfcth, 2048, 2048);
    k_cat3<<<(NDOWN + 255) / 256, 256>>>((float*)p_bd, bdq, bdkv, bkr, 512, 512, 512);
    k_cat2<<<(NQ + 255) / 256, 256>>>((float*)p_bq, buq, bqr, UPx, RRx * HHx);
    k_cat2<<<(NKV + 255) / 256, 256>>>((float*)p_bkv, buk, buv, UPx, UPx);

    // fused down-proj: M=4096, N=1536, K=2048 (split output)
    k_gemm<<<dim3(12, 32, 1), 256, SMEMB>>>(
        (uint16_t*)p_xsh, (uint16_t*)p_xsl, DDx, 0,
        (uint16_t*)p_wdth, DDx, 0,
        nullptr, (uint16_t*)p_d0sh, (uint16_t*)p_d0sl, NDOWN, 0, 0,
        (float*)p_bd, 1.f, DDx, 0, 1);

    // merged q-side up-proj with fused rope+split: M=4096, N=10240, K=512
    k_gemm<<<dim3(80, 32, 1), 256, SMEMB>>>(
        (uint16_t*)p_d0sh, (uint16_t*)p_d0sl, NDOWN, 0,
        (uint16_t*)p_wqth, DWN, 0,
        nullptr, (uint16_t*)p_quh, (uint16_t*)p_qul, NQ, 0, 0,
        (float*)p_bq, 1.f, DWN, 1, 1);
    // merged kv-side up-proj: K content fp16 + V fp32: M=4096, N=4096, K=512
    k_gemm<<<dim3(32, 32, 1), 256, SMEMB>>>(
        (uint16_t*)p_d0sh + 512, (uint16_t*)p_d0sl + 512, NDOWN, 0,
        (uint16_t*)p_wkvth, DWN, 0,
        (float*)p_vf, (uint16_t*)p_kch, nullptr, 2048, 0, 0,
        (float*)p_bkv, 1.f, DWN, 2, 1);

    k_rope_k<<<MROWS, 256>>>();
    k_vt<<<dim3(16, 4, ZBx), tb>>>();

    // scores: per z M=512, N=512, K=640, piecewise q/k sources
    k_gemm_qk<<<dim3(4, 4, ZBx), 256, SMEMB>>>();

    k_softmax<<<ZBx * SSx, 128>>>();

    // PV: per z M=512, N=128, K=512, single-plane A (probs fp16)
    k_gemm<<<dim3(1, 4, ZBx), 256, SMEMB>>>(
        (uint16_t*)p_psh, (uint16_t*)p_psh, SSx, (long long)SSx * SSx,
        (uint16_t*)p_vtsh, SSx, (long long)VHDx * SSx,
        nullptr, (uint16_t*)p_ofsh, (uint16_t*)p_ofsl, UPx,
        (long long)SSx * UPx, (long long)VHDx,
        nullptr, 1.f, SSx, 0, 0);

    // final: M=4096, N=2048, K=2048 -> out fp32
    k_gemm<<<dim3(16, 32, 1), 256, SMEMB>>>(
        (uint16_t*)p_ofsh, (uint16_t*)p_ofsl, UPx, 0,
        (uint16_t*)p_wfcth, DDx, 0,
        out, nullptr, nullptr, DDx, 0, 0, bfc, 1.f, DDx, 0, 1);
}

// round 13
// speedup vs baseline: 1.0832x; 1.0449x over previous
#include <cuda_runtime.h>
#include <cuda_fp16.h>
#include <cstdint>
#include <math.h>

#define BBx   8
#define SSx   512
#define DDx   2048
#define HHx   16
#define DWN   512
#define UPx   2048
#define RRx   512
#define VHDx  128
#define MROWS (BBx*SSx)
#define ZBx   (BBx*HHx)
#define QKD   (VHDx+RRx)
#define NDOWN (DWN*3)
#define NQ    (UPx + RRx*HHx)     // 10240  (qc | qr)
#define NKV   (UPx + UPx)         // 4096   (kc | vc)
#define INV_SCALE 0.0294627825494394758f

// fp16 planes. "split" tensors have hi+lo; others single plane.
__device__ uint16_t g_xh  [(size_t)MROWS*DDx];      // X single plane
__device__ uint16_t g_wdth[(size_t)NDOWN*DDx];      // B
__device__ float    g_bd  [NDOWN];
__device__ uint16_t g_wqth[(size_t)NQ*DWN];         // B
__device__ uint16_t g_wkvth[(size_t)NKV*DWN];       // B
__device__ float    g_bq  [NQ];
__device__ float    g_bkv [NKV];
__device__ uint16_t g_wfcth[(size_t)DDx*DDx];       // B
__device__ uint16_t g_d0sh[(size_t)MROWS*NDOWN];
__device__ uint16_t g_d0sl[(size_t)MROWS*NDOWN];
__device__ uint16_t g_quh [(size_t)MROWS*NQ];
__device__ uint16_t g_qul [(size_t)MROWS*NQ];
__device__ uint16_t g_kch [(size_t)MROWS*UPx];
__device__ float    g_vf  [(size_t)MROWS*UPx];
__device__ uint16_t g_krh [(size_t)MROWS*RRx];
__device__ float    g_sc  [(size_t)ZBx*SSx*SSx];
__device__ uint16_t g_psh [(size_t)ZBx*SSx*SSx];    // probs single plane
__device__ uint16_t g_vtsh[(size_t)ZBx*VHDx*SSx];   // B
__device__ uint16_t g_ofsh[(size_t)MROWS*UPx];      // O single plane
__device__ float    g_sin [SSx*(RRx/2)];
__device__ float    g_cos [SSx*(RRx/2)];

__device__ __forceinline__ uint32_t smem_u32(const void* p) {
    uint32_t a;
    asm("{ .reg .u64 t; cvta.to.shared.u64 t, %1; cvt.u32.u64 %0, t; }" : "=r"(a) : "l"(p));
    return a;
}
__device__ __forceinline__ void split1(float v, uint16_t& h, uint16_t& l) {
    __half hb = __float2half_rn(v);
    __half lb = __float2half_rn(v - __half2float(hb));
    h = __half_as_ushort(hb); l = __half_as_ushort(lb);
}
__device__ __forceinline__ uint2 split2(float a, float b) {
    uint16_t ah, al, bh, bl; split1(a, ah, al); split1(b, bh, bl);
    return make_uint2((uint32_t)ah | ((uint32_t)bh << 16),
                      (uint32_t)al | ((uint32_t)bl << 16));
}
__device__ __forceinline__ uint32_t h2pack(float a, float b) {
    __half2 h = __floats2half2_rn(a, b);
    return *(uint32_t*)&h;
}
__device__ __forceinline__ float join1(uint16_t h, uint16_t l) {
    return __half2float(__ushort_as_half(h)) + __half2float(__ushort_as_half(l));
}
__device__ __forceinline__ void ldm4(uint32_t* r, uint32_t addr) {
    asm volatile("ldmatrix.sync.aligned.m8n8.x4.shared.b16 {%0,%1,%2,%3}, [%4];"
        : "=r"(r[0]), "=r"(r[1]), "=r"(r[2]), "=r"(r[3]) : "r"(addr));
}
__device__ __forceinline__ void mma16816(float* c, const uint32_t* a, const uint32_t* b) {
    asm volatile("mma.sync.aligned.m16n8k16.row.col.f32.f16.f16.f32 "
        "{%0,%1,%2,%3}, {%4,%5,%6,%7}, {%8,%9}, {%0,%1,%2,%3};"
        : "+f"(c[0]), "+f"(c[1]), "+f"(c[2]), "+f"(c[3])
        : "r"(a[0]), "r"(a[1]), "r"(a[2]), "r"(a[3]), "r"(b[0]), "r"(b[1]));
}
#define CP16(dst, src) \
    asm volatile("cp.async.cg.shared.global [%0], [%1], 16;" :: "r"(dst), "l"(src))
#define CP_COMMIT() asm volatile("cp.async.commit_group;" ::: "memory")
#define CP_WAIT0()  asm volatile("cp.async.wait_group 0;" ::: "memory")

#define PITCH  80
#define PLA_L  (128*PITCH)
#define STG_L  (3*PLA_L)          // 30720 per stage
#define SMEMB  (2*STG_L)          // 61440 -> 2 CTAs/SM

// ------------------ generic GEMM: C = scale*(A @ B^T) + bias --------------------
// emode 0: std (fp32 Cf and/or split Csh/Csl, z-scatter)
// emode 1: q-up rope + split store
// emode 2: kv-up (K fp16 / V fp32)
// emode 3: single fp16 plane store to Csh with z-scatter
// aSplit: 1 = A hi+lo planes (2 mmas); 0 = A single plane (1 mma)
__global__ void __launch_bounds__(256, 2) k_gemm(
    const uint16_t* __restrict__ Ah, const uint16_t* __restrict__ Al, int lda, long long aB,
    const uint16_t* __restrict__ Bh, int ldb, long long bB,
    float* Cf, uint16_t* Csh, uint16_t* Csl, int ldc, long long cO, long long cI,
    const float* __restrict__ bias, float scale, int K, int emode, int aSplit)
{
    extern __shared__ __align__(16) char smem[];
    const uint32_t sb = smem_u32(smem);
    const int tid = threadIdx.x, lane = tid & 31, wid = tid >> 5;
    const int wm = wid >> 1, wn = wid & 1;     // 4m x 2n
    const int z = blockIdx.z, bm = blockIdx.y, bn = blockIdx.x;

    const uint16_t* pb0 = Ah + (size_t)z * aB + (size_t)bm * 128 * lda;
    const uint16_t* pb1 = Al + (size_t)z * aB + (size_t)bm * 128 * lda;
    const uint16_t* pb2 = Bh + (size_t)z * bB + (size_t)bn * 128 * ldb;
    const int nCh = K / 32;

    auto issue = [&](int c) {
        if (c < nCh) {
            const int kc = c * 32;
            const uint32_t sdst = sb + (c & 1) * STG_L;
            const int row = (tid >> 2);
            const int col16 = (tid & 3);
            #pragma unroll
            for (int p = 0; p < 6; p++) {
                const int pl = p >> 1;
                if (pl == 1 && !aSplit) continue;
                const int r = (p & 1) * 64 + row;
                const uint16_t* src = (pl == 0 ? pb0 : pl == 1 ? pb1 : pb2);
                const int ld = (pl < 2) ? lda : ldb;
                CP16(sdst + pl * PLA_L + r * PITCH + col16 * 16,
                     src + (size_t)r * ld + kc + col16 * 8);
            }
            CP_COMMIT();
        }
    };

    float acc[2][8][4];
    #pragma unroll
    for (int i = 0; i < 2; i++)
        #pragma unroll
        for (int j = 0; j < 8; j++)
            #pragma unroll
            for (int r = 0; r < 4; r++) acc[i][j][r] = 0.f;

    issue(0);

    for (int c = 0; c < nCh; c++) {
        CP_WAIT0();
        __syncthreads();
        issue(c + 1);

        const uint32_t sbuf = sb + (c & 1) * STG_L;
        #pragma unroll
        for (int k16 = 0; k16 < 2; k16++) {
            uint32_t af[2][2][4];
            uint32_t abase = sbuf + (wm * 32 + (lane & 15)) * PITCH
                           + (k16 * 16 + (lane >> 4) * 8) * 2;
            #pragma unroll
            for (int mt = 0; mt < 2; mt++) {
                ldm4(af[0][mt], abase + mt * 16 * PITCH);
                if (aSplit) ldm4(af[1][mt], abase + PLA_L + mt * 16 * PITCH);
            }
            uint32_t bbase = sbuf + 2 * PLA_L
                + (wn * 64 + (lane & 7) + ((lane >> 4) << 3)) * PITCH
                + (k16 * 16 + ((lane >> 3) & 1) * 8) * 2;
            #pragma unroll
            for (int nb = 0; nb < 4; nb++) {
                uint32_t bh[4];
                ldm4(bh, bbase + nb * 16 * PITCH);
                #pragma unroll
                for (int hf = 0; hf < 2; hf++) {
                    const int nt = nb * 2 + hf;
                    #pragma unroll
                    for (int mt = 0; mt < 2; mt++) {
                        mma16816(acc[mt][nt], af[0][mt], &bh[2 * hf]);
                        if (aSplit) mma16816(acc[mt][nt], af[1][mt], &bh[2 * hf]);
                    }
                }
            }
        }
    }

    const long long coff = (long long)(z >> 4) * cO + (long long)(z & 15) * cI;
    #pragma unroll
    for (int nt = 0; nt < 8; nt++) {
        const int gc = bn * 128 + wn * 64 + nt * 8 + (lane & 3) * 2;
        float2 bv = make_float2(0.f, 0.f);
        if (bias) bv = *(const float2*)(bias + gc);
        #pragma unroll
        for (int mt = 0; mt < 2; mt++) {
            const int r0 = bm * 128 + wm * 32 + mt * 16 + (lane >> 2);
            #pragma unroll
            for (int half = 0; half < 2; half++) {
                const int grow = r0 + half * 8;
                float v0 = acc[mt][nt][2 * half + 0] * scale + bv.x;
                float v1 = acc[mt][nt][2 * half + 1] * scale + bv.y;
                if (emode == 0) {
                    const long long gp = coff + (long long)grow * ldc + gc;
                    if (Cf) *(float2*)(Cf + gp) = make_float2(v0, v1);
                    if (Csh) {
                        uint2 s = split2(v0, v1);
                        *(uint32_t*)(Csh + gp) = s.x;
                        *(uint32_t*)(Csl + gp) = s.y;
                    }
                } else if (emode == 1) {
                    if (gc >= 2048) {
                        const int s = grow & (SSx - 1);
                        const int i2 = (gc - 2048) & (RRx - 1);
                        const int ii = s * 256 + (i2 >> 1);
                        float sn = g_sin[ii], cs = g_cos[ii];
                        float o0 = v0 * cs - v1 * sn;
                        float o1 = v1 * cs + v0 * sn;
                        v0 = o0; v1 = o1;
                    }
                    const long long gp = (long long)grow * ldc + gc;
                    uint2 s = split2(v0, v1);
                    *(uint32_t*)(Csh + gp) = s.x;
                    *(uint32_t*)(Csl + gp) = s.y;
                } else if (emode == 2) {
                    if (gc < 2048)
                        *(uint32_t*)(Csh + (long long)grow * 2048 + gc) = h2pack(v0, v1);
                    else
                        *(float2*)(Cf + (long long)grow * 2048 + gc - 2048) =
                            make_float2(v0, v1);
                } else {   // emode == 3: single fp16 plane, z-scatter
                    const long long gp = coff + (long long)grow * ldc + gc;
                    *(uint32_t*)(Csh + gp) = h2pack(v0, v1);
                }
            }
        }
    }
}

// ------------------ scores GEMM with piecewise q/k addressing -------------------
__global__ void __launch_bounds__(256, 2) k_gemm_qk()
{
    extern __shared__ __align__(16) char smem[];
    const uint32_t sb = smem_u32(smem);
    const int tid = threadIdx.x, lane = tid & 31, wid = tid >> 5;
    const int wm = wid >> 1, wn = wid & 1;
    const int z = blockIdx.z, bm = blockIdx.y, bn = blockIdx.x;
    const int b = z >> 4, h = z & 15;
    const long long gRow0 = (long long)b * SSx + bm * 128;
    const long long kRow0 = (long long)b * SSx + bn * 128;
    const int nCh = QKD / 32;    // 20

    auto issue = [&](int c) {
        if (c < nCh) {
            const uint32_t sdst = sb + (c & 1) * STG_L;
            const int row = (tid >> 2);
            const int col16 = (tid & 3);
            const int colA = (c < 4) ? (h * VHDx + c * 32)
                                     : (2048 + h * RRx + (c - 4) * 32);
            #pragma unroll
            for (int p = 0; p < 6; p++) {
                const int pl = p >> 1;
                const int r = (p & 1) * 64 + row;
                uint32_t dst = sdst + pl * PLA_L + r * PITCH + col16 * 16;
                if (pl == 0) {
                    CP16(dst, g_quh + (gRow0 + r) * NQ + colA + col16 * 8);
                } else if (pl == 1) {
                    CP16(dst, g_qul + (gRow0 + r) * NQ + colA + col16 * 8);
                } else {
                    if (c < 4)
                        CP16(dst, g_kch + (kRow0 + r) * UPx + h * VHDx + c * 32 + col16 * 8);
                    else
                        CP16(dst, g_krh + (kRow0 + r) * RRx + (c - 4) * 32 + col16 * 8);
                }
            }
            CP_COMMIT();
        }
    };

    float acc[2][8][4];
    #pragma unroll
    for (int i = 0; i < 2; i++)
        #pragma unroll
        for (int j = 0; j < 8; j++)
            #pragma unroll
            for (int r = 0; r < 4; r++) acc[i][j][r] = 0.f;

    issue(0);

    for (int c = 0; c < nCh; c++) {
        CP_WAIT0();
        __syncthreads();
        issue(c + 1);

        const uint32_t sbuf = sb + (c & 1) * STG_L;
        #pragma unroll
        for (int k16 = 0; k16 < 2; k16++) {
            uint32_t af[2][2][4];
            uint32_t abase = sbuf + (wm * 32 + (lane & 15)) * PITCH
                           + (k16 * 16 + (lane >> 4) * 8) * 2;
            #pragma unroll
            for (int mt = 0; mt < 2; mt++) {
                ldm4(af[0][mt], abase + mt * 16 * PITCH);
                ldm4(af[1][mt], abase + PLA_L + mt * 16 * PITCH);
            }
            uint32_t bbase = sbuf + 2 * PLA_L
                + (wn * 64 + (lane & 7) + ((lane >> 4) << 3)) * PITCH
                + (k16 * 16 + ((lane >> 3) & 1) * 8) * 2;
            #pragma unroll
            for (int nb = 0; nb < 4; nb++) {
                uint32_t bh[4];
                ldm4(bh, bbase + nb * 16 * PITCH);
                #pragma unroll
                for (int hf = 0; hf < 2; hf++) {
                    const int nt = nb * 2 + hf;
                    #pragma unroll
                    for (int mt = 0; mt < 2; mt++) {
                        mma16816(acc[mt][nt], af[0][mt], &bh[2 * hf]);
                        mma16816(acc[mt][nt], af[1][mt], &bh[2 * hf]);
                    }
                }
            }
        }
    }

    float* C = g_sc + (size_t)z * SSx * SSx;
    #pragma unroll
    for (int nt = 0; nt < 8; nt++) {
        const int gc = bn * 128 + wn * 64 + nt * 8 + (lane & 3) * 2;
        #pragma unroll
        for (int mt = 0; mt < 2; mt++) {
            const int r0 = bm * 128 + wm * 32 + mt * 16 + (lane >> 2);
            #pragma unroll
            for (int half = 0; half < 2; half++) {
                const long long gp = (long long)(r0 + half * 8) * SSx + gc;
                *(float2*)(C + gp) = make_float2(
                    acc[mt][nt][2 * half + 0] * INV_SCALE,
                    acc[mt][nt][2 * half + 1] * INV_SCALE);
            }
        }
    }
}

__global__ void k_half_x(const float* __restrict__ s, uint16_t* __restrict__ dh, int n2) {
    int i = blockIdx.x * 256 + threadIdx.x;
    if (i < n2) {
        float2 v = *(const float2*)(s + 2 * i);
        *(uint32_t*)(dh + 2 * i) = h2pack(v.x, v.y);
    }
}
__global__ void k_trsp(const float* __restrict__ W, uint16_t* __restrict__ Wth,
                       int Kd, int Nd) {
    __shared__ float t[32][33];
    int n0 = blockIdx.x * 32, k0 = blockIdx.y * 32;
    int tx = threadIdx.x, ty = threadIdx.y;
    #pragma unroll
    for (int i = 0; i < 32; i += 8)
        t[ty + i][tx] = W[(size_t)(k0 + ty + i) * Nd + n0 + tx];
    __syncthreads();
    #pragma unroll
    for (int i = 0; i < 32; i += 8)
        Wth[(size_t)(n0 + ty + i) * Kd + k0 + tx] =
            __half_as_ushort(__float2half_rn(t[tx][ty + i]));
}
__global__ void k_cat3(float* dst, const float* a, const float* b, const float* c,
                       int na, int nb, int nc) {
    int i = blockIdx.x * 256 + threadIdx.x;
    if (i < na) dst[i] = a[i];
    else if (i < na + nb) dst[i] = b[i - na];
    else if (i < na + nb + nc) dst[i] = c[i - na - nb];
}
__global__ void k_cat2(float* dst, const float* a, const float* b, int na, int nb) {
    int i = blockIdx.x * 256 + threadIdx.x;
    if (i < na) dst[i] = a[i];
    else if (i < na + nb) dst[i] = b[i - na];
}
__global__ void k_table() {
    int idx = blockIdx.x * 256 + threadIdx.x;
    int s = idx >> 8, i = idx & 255;
    float dv = expf((float)(2 * i) * (-9.210340371976184f / (float)RRx));
    float sn, cs; sincosf((float)s * dv, &sn, &cs);
    g_sin[idx] = sn; g_cos[idx] = cs;
}
__global__ void k_rope_k() {
    int idx = blockIdx.x * 256 + threadIdx.x;
    int i = idx & 255, row = idx >> 8, s = row & (SSx - 1);
    size_t o = (size_t)row * NDOWN + 1024 + 2 * i;
    float vx = join1(g_d0sh[o],     g_d0sl[o]);
    float vy = join1(g_d0sh[o + 1], g_d0sl[o + 1]);
    float sn = g_sin[s * 256 + i], cs = g_cos[s * 256 + i];
    *(uint32_t*)(g_krh + (size_t)row * RRx + 2 * i) =
        h2pack(vx * cs - vy * sn, vy * cs + vx * sn);
}
__global__ void k_vt() {
    __shared__ float t[32][33];
    int z = blockIdx.z, b = z >> 4, h = z & 15;
    int s0 = blockIdx.x * 32, d0 = blockIdx.y * 32;
    int tx = threadIdx.x, ty = threadIdx.y;
    #pragma unroll
    for (int i = 0; i < 32; i += 8)
        t[ty + i][tx] = g_vf[(size_t)(b * SSx + s0 + ty + i) * UPx + h * VHDx + d0 + tx];
    __syncthreads();
    #pragma unroll
    for (int i = 0; i < 32; i += 8)
        g_vtsh[(size_t)z * (VHDx * SSx) + (size_t)(d0 + ty + i) * SSx + s0 + tx] =
            __half_as_ushort(__float2half_rn(t[tx][ty + i]));
}
__global__ void __launch_bounds__(128) k_softmax() {
    size_t row = blockIdx.x;
    const float* p = g_sc + row * SSx;
    int t = threadIdx.x;
    float4 v = ((const float4*)p)[t];
    float m = fmaxf(fmaxf(v.x, v.y), fmaxf(v.z, v.w));
    #pragma unroll
    for (int o = 16; o; o >>= 1) m = fmaxf(m, __shfl_xor_sync(0xffffffffu, m, o));
    __shared__ float rm[4], rs[4];
    if ((t & 31) == 0) rm[t >> 5] = m;
    __syncthreads();
    m = fmaxf(fmaxf(rm[0], rm[1]), fmaxf(rm[2], rm[3]));
    v.x = __expf(v.x - m); v.y = __expf(v.y - m);
    v.z = __expf(v.z - m); v.w = __expf(v.w - m);
    float s = v.x + v.y + v.z + v.w;
    #pragma unroll
    for (int o = 16; o; o >>= 1) s += __shfl_xor_sync(0xffffffffu, s, o);
    if ((t & 31) == 0) rs[t >> 5] = s;
    __syncthreads();
    s = rs[0] + rs[1] + rs[2] + rs[3];
    float inv = 1.f / s;
    *(uint2*)(g_psh + row * SSx + t * 4) =
        make_uint2(h2pack(v.x * inv, v.y * inv), h2pack(v.z * inv, v.w * inv));
}

extern "C" void kernel_launch(void* const* d_in, const int* in_sizes, int n_in,
                              void* d_out, int out_size)
{
    const float* X    = (const float*)d_in[0];
    const float* Wdq  = (const float*)d_in[1];
    const float* bdq  = (const float*)d_in[2];
    const float* Wdkv = (const float*)d_in[3];
    const float* bdkv = (const float*)d_in[4];
    const float* Wuq  = (const float*)d_in[5];
    const float* buq  = (const float*)d_in[6];
    const float* Wuk  = (const float*)d_in[7];
    const float* buk  = (const float*)d_in[8];
    const float* Wuv  = (const float*)d_in[9];
    const float* buv  = (const float*)d_in[10];
    const float* Wqr  = (const float*)d_in[11];
    const float* bqr  = (const float*)d_in[12];
    const float* Wkr  = (const float*)d_in[13];
    const float* bkr  = (const float*)d_in[14];
    const float* Wfc  = (const float*)d_in[15];
    const float* bfc  = (const float*)d_in[16];
    float* out = (float*)d_out;

    cudaFuncSetAttribute(k_gemm, cudaFuncAttributeMaxDynamicSharedMemorySize, SMEMB);
    cudaFuncSetAttribute(k_gemm_qk, cudaFuncAttributeMaxDynamicSharedMemorySize, SMEMB);

    #define SYM(v, g) void* v; cudaGetSymbolAddress(&v, g)
    SYM(p_xh, g_xh);
    SYM(p_wdth, g_wdth); SYM(p_bd, g_bd);
    SYM(p_wqth, g_wqth); SYM(p_wkvth, g_wkvth);
    SYM(p_bq, g_bq); SYM(p_bkv, g_bkv);
    SYM(p_wfcth, g_wfcth);
    SYM(p_d0sh, g_d0sh); SYM(p_d0sl, g_d0sl);
    SYM(p_quh, g_quh); SYM(p_qul, g_qul);
    SYM(p_kch, g_kch); SYM(p_vf, g_vf);
    SYM(p_sc, g_sc); SYM(p_psh, g_psh);
    SYM(p_vtsh, g_vtsh);
    SYM(p_ofsh, g_ofsh);
    #undef SYM

    dim3 tb(32, 8);
    k_table<<<SSx, 256>>>();
    k_half_x<<<(MROWS * DDx / 2) / 256, 256>>>(X, (uint16_t*)p_xh, MROWS * DDx / 2);
    k_trsp<<<dim3(16, 64), tb>>>(Wdq,  (uint16_t*)p_wdth, 2048, 512);
    k_trsp<<<dim3(16, 64), tb>>>(Wdkv, (uint16_t*)p_wdth + (size_t)512 * 2048, 2048, 512);
    k_trsp<<<dim3(16, 64), tb>>>(Wkr,  (uint16_t*)p_wdth + (size_t)1024 * 2048, 2048, 512);
    k_trsp<<<dim3(64, 16), tb>>>(Wuq, (uint16_t*)p_wqth, 512, 2048);
    k_trsp<<<dim3(256, 16), tb>>>(Wqr, (uint16_t*)p_wqth + (size_t)UPx * 512, 512, 8192);
    k_trsp<<<dim3(64, 16), tb>>>(Wuk, (uint16_t*)p_wkvth, 512, 2048);
    k_trsp<<<dim3(64, 16), tb>>>(Wuv, (uint16_t*)p_wkvth + (size_t)UPx * 512, 512, 2048);
    k_trsp<<<dim3(64, 64), tb>>>(Wfc, (uint16_t*)p_wfcth, 2048, 2048);
    k_cat3<<<(NDOWN + 255) / 256, 256>>>((float*)p_bd, bdq, bdkv, bkr, 512, 512, 512);
    k_cat2<<<(NQ + 255) / 256, 256>>>((float*)p_bq, buq, bqr, UPx, RRx * HHx);
    k_cat2<<<(NKV + 255) / 256, 256>>>((float*)p_bkv, buk, buv, UPx, UPx);

    // fused down-proj: M=4096, N=1536, K=2048, single-plane X A-side
    k_gemm<<<dim3(12, 32, 1), 256, SMEMB>>>(
        (uint16_t*)p_xh, (uint16_t*)p_xh, DDx, 0,
        (uint16_t*)p_wdth, DDx, 0,
        nullptr, (uint16_t*)p_d0sh, (uint16_t*)p_d0sl, NDOWN, 0, 0,
        (float*)p_bd, 1.f, DDx, 0, 0);

    // merged q-side up-proj with fused rope+split: M=4096, N=10240, K=512
    k_gemm<<<dim3(80, 32, 1), 256, SMEMB>>>(
        (uint16_t*)p_d0sh, (uint16_t*)p_d0sl, NDOWN, 0,
        (uint16_t*)p_wqth, DWN, 0,
        nullptr, (uint16_t*)p_quh, (uint16_t*)p_qul, NQ, 0, 0,
        (float*)p_bq, 1.f, DWN, 1, 1);
    // merged kv-side up-proj: K content fp16 + V fp32: M=4096, N=4096, K=512
    k_gemm<<<dim3(32, 32, 1), 256, SMEMB>>>(
        (uint16_t*)p_d0sh + 512, (uint16_t*)p_d0sl + 512, NDOWN, 0,
        (uint16_t*)p_wkvth, DWN, 0,
        (float*)p_vf, (uint16_t*)p_kch, nullptr, 2048, 0, 0,
        (float*)p_bkv, 1.f, DWN, 2, 1);

    k_rope_k<<<MROWS, 256>>>();
    k_vt<<<dim3(16, 4, ZBx), tb>>>();

    // scores: per z M=512, N=512, K=640, piecewise q/k sources
    k_gemm_qk<<<dim3(4, 4, ZBx), 256, SMEMB>>>();

    k_softmax<<<ZBx * SSx, 128>>>();

    // PV: per z M=512, N=128, K=512, single-plane A (probs), single-plane O out
    k_gemm<<<dim3(1, 4, ZBx), 256, SMEMB>>>(
        (uint16_t*)p_psh, (uint16_t*)p_psh, SSx, (long long)SSx * SSx,
        (uint16_t*)p_vtsh, SSx, (long long)VHDx * SSx,
        nullptr, (uint16_t*)p_ofsh, nullptr, UPx,
        (long long)SSx * UPx, (long long)VHDx,
        nullptr, 1.f, SSx, 3, 0);

    // final: M=4096, N=2048, K=2048, single-plane O A-side -> out fp32
    k_gemm<<<dim3(16, 32, 1), 256, SMEMB>>>(
        (uint16_t*)p_ofsh, (uint16_t*)p_ofsh, UPx, 0,
        (uint16_t*)p_wfcth, DDx, 0,
        out, nullptr, nullptr, DDx, 0, 0, bfc, 1.f, DDx, 0, 0);
}

// round 14
// speedup vs baseline: 1.1955x; 1.1036x over previous
#include <cuda_runtime.h>
#include <cuda_fp16.h>
#include <cstdint>
#include <math.h>

#define BBx   8
#define SSx   512
#define DDx   2048
#define HHx   16
#define DWN   512
#define UPx   2048
#define RRx   512
#define VHDx  128
#define MROWS (BBx*SSx)
#define ZBx   (BBx*HHx)
#define QKD   (VHDx+RRx)
#define NDOWN (DWN*3)
#define NQ    (UPx + RRx*HHx)     // 10240  (qc | qr)
#define NKV   (UPx + UPx)         // 4096   (kc | vc)
#define INV_SCALE 0.0294627825494394758f

// fp16 planes. "split" tensors have hi+lo; others single plane.
__device__ uint16_t g_xh  [(size_t)MROWS*DDx];      // X single plane
__device__ uint16_t g_wdth[(size_t)NDOWN*DDx];      // B
__device__ float    g_bd  [NDOWN];
__device__ uint16_t g_wqth[(size_t)NQ*DWN];         // B
__device__ uint16_t g_wkvth[(size_t)NKV*DWN];       // B
__device__ float    g_bq  [NQ];
__device__ float    g_bkv [NKV];
__device__ uint16_t g_wfcth[(size_t)DDx*DDx];       // B
__device__ uint16_t g_d0sh[(size_t)MROWS*NDOWN];
__device__ uint16_t g_d0sl[(size_t)MROWS*NDOWN];
__device__ uint16_t g_quh [(size_t)MROWS*NQ];       // q roped: single fp16 plane
__device__ uint16_t g_kch [(size_t)MROWS*UPx];
__device__ float    g_vf  [(size_t)MROWS*UPx];
__device__ uint16_t g_krh [(size_t)MROWS*RRx];
__device__ float    g_sc  [(size_t)ZBx*SSx*SSx];
__device__ uint16_t g_psh [(size_t)ZBx*SSx*SSx];    // probs single plane
__device__ uint16_t g_vtsh[(size_t)ZBx*VHDx*SSx];   // B
__device__ uint16_t g_ofsh[(size_t)MROWS*UPx];      // O single plane
__device__ float    g_sin [SSx*(RRx/2)];
__device__ float    g_cos [SSx*(RRx/2)];

__device__ __forceinline__ uint32_t smem_u32(const void* p) {
    uint32_t a;
    asm("{ .reg .u64 t; cvta.to.shared.u64 t, %1; cvt.u32.u64 %0, t; }" : "=r"(a) : "l"(p));
    return a;
}
__device__ __forceinline__ void split1(float v, uint16_t& h, uint16_t& l) {
    __half hb = __float2half_rn(v);
    __half lb = __float2half_rn(v - __half2float(hb));
    h = __half_as_ushort(hb); l = __half_as_ushort(lb);
}
__device__ __forceinline__ uint2 split2(float a, float b) {
    uint16_t ah, al, bh, bl; split1(a, ah, al); split1(b, bh, bl);
    return make_uint2((uint32_t)ah | ((uint32_t)bh << 16),
                      (uint32_t)al | ((uint32_t)bl << 16));
}
__device__ __forceinline__ uint32_t h2pack(float a, float b) {
    __half2 h = __floats2half2_rn(a, b);
    return *(uint32_t*)&h;
}
__device__ __forceinline__ float join1(uint16_t h, uint16_t l) {
    return __half2float(__ushort_as_half(h)) + __half2float(__ushort_as_half(l));
}
__device__ __forceinline__ void ldm4(uint32_t* r, uint32_t addr) {
    asm volatile("ldmatrix.sync.aligned.m8n8.x4.shared.b16 {%0,%1,%2,%3}, [%4];"
        : "=r"(r[0]), "=r"(r[1]), "=r"(r[2]), "=r"(r[3]) : "r"(addr));
}
__device__ __forceinline__ void mma16816(float* c, const uint32_t* a, const uint32_t* b) {
    asm volatile("mma.sync.aligned.m16n8k16.row.col.f32.f16.f16.f32 "
        "{%0,%1,%2,%3}, {%4,%5,%6,%7}, {%8,%9}, {%0,%1,%2,%3};"
        : "+f"(c[0]), "+f"(c[1]), "+f"(c[2]), "+f"(c[3])
        : "r"(a[0]), "r"(a[1]), "r"(a[2]), "r"(a[3]), "r"(b[0]), "r"(b[1]));
}
#define CP16(dst, src) \
    asm volatile("cp.async.cg.shared.global [%0], [%1], 16;" :: "r"(dst), "l"(src))
#define CP_COMMIT() asm volatile("cp.async.commit_group;" ::: "memory")
#define CP_WAIT0()  asm volatile("cp.async.wait_group 0;" ::: "memory")

#define PITCH  80
#define PLA_L  (128*PITCH)
#define STG_L  (3*PLA_L)          // 30720 per stage
#define SMEMB  (2*STG_L)          // 61440 -> 2 CTAs/SM

// ------------------ generic GEMM: C = scale*(A @ B^T) + bias --------------------
// emode 0: std (fp32 Cf and/or split Csh/Csl, z-scatter)
// emode 1: q-up rope + SINGLE fp16 plane store
// emode 2: kv-up (K fp16 / V fp32)
// emode 3: single fp16 plane store to Csh with z-scatter
// aSplit: 1 = A hi+lo planes (2 mmas); 0 = A single plane (1 mma)
__global__ void __launch_bounds__(256, 2) k_gemm(
    const uint16_t* __restrict__ Ah, const uint16_t* __restrict__ Al, int lda, long long aB,
    const uint16_t* __restrict__ Bh, int ldb, long long bB,
    float* Cf, uint16_t* Csh, uint16_t* Csl, int ldc, long long cO, long long cI,
    const float* __restrict__ bias, float scale, int K, int emode, int aSplit)
{
    extern __shared__ __align__(16) char smem[];
    const uint32_t sb = smem_u32(smem);
    const int tid = threadIdx.x, lane = tid & 31, wid = tid >> 5;
    const int wm = wid >> 1, wn = wid & 1;     // 4m x 2n
    const int z = blockIdx.z, bm = blockIdx.y, bn = blockIdx.x;

    const uint16_t* pb0 = Ah + (size_t)z * aB + (size_t)bm * 128 * lda;
    const uint16_t* pb1 = Al + (size_t)z * aB + (size_t)bm * 128 * lda;
    const uint16_t* pb2 = Bh + (size_t)z * bB + (size_t)bn * 128 * ldb;
    const int nCh = K / 32;

    auto issue = [&](int c) {
        if (c < nCh) {
            const int kc = c * 32;
            const uint32_t sdst = sb + (c & 1) * STG_L;
            const int row = (tid >> 2);
            const int col16 = (tid & 3);
            #pragma unroll
            for (int p = 0; p < 6; p++) {
                const int pl = p >> 1;
                if (pl == 1 && !aSplit) continue;
                const int r = (p & 1) * 64 + row;
                const uint16_t* src = (pl == 0 ? pb0 : pl == 1 ? pb1 : pb2);
                const int ld = (pl < 2) ? lda : ldb;
                CP16(sdst + pl * PLA_L + r * PITCH + col16 * 16,
                     src + (size_t)r * ld + kc + col16 * 8);
            }
            CP_COMMIT();
        }
    };

    float acc[2][8][4];
    #pragma unroll
    for (int i = 0; i < 2; i++)
        #pragma unroll
        for (int j = 0; j < 8; j++)
            #pragma unroll
            for (int r = 0; r < 4; r++) acc[i][j][r] = 0.f;

    issue(0);

    for (int c = 0; c < nCh; c++) {
        CP_WAIT0();
        __syncthreads();
        issue(c + 1);

        const uint32_t sbuf = sb + (c & 1) * STG_L;
        #pragma unroll
        for (int k16 = 0; k16 < 2; k16++) {
            uint32_t af[2][2][4];
            uint32_t abase = sbuf + (wm * 32 + (lane & 15)) * PITCH
                           + (k16 * 16 + (lane >> 4) * 8) * 2;
            #pragma unroll
            for (int mt = 0; mt < 2; mt++) {
                ldm4(af[0][mt], abase + mt * 16 * PITCH);
                if (aSplit) ldm4(af[1][mt], abase + PLA_L + mt * 16 * PITCH);
            }
            uint32_t bbase = sbuf + 2 * PLA_L
                + (wn * 64 + (lane & 7) + ((lane >> 4) << 3)) * PITCH
                + (k16 * 16 + ((lane >> 3) & 1) * 8) * 2;
            #pragma unroll
            for (int nb = 0; nb < 4; nb++) {
                uint32_t bh[4];
                ldm4(bh, bbase + nb * 16 * PITCH);
                #pragma unroll
                for (int hf = 0; hf < 2; hf++) {
                    const int nt = nb * 2 + hf;
                    #pragma unroll
                    for (int mt = 0; mt < 2; mt++) {
                        mma16816(acc[mt][nt], af[0][mt], &bh[2 * hf]);
                        if (aSplit) mma16816(acc[mt][nt], af[1][mt], &bh[2 * hf]);
                    }
                }
            }
        }
    }

    const long long coff = (long long)(z >> 4) * cO + (long long)(z & 15) * cI;
    #pragma unroll
    for (int nt = 0; nt < 8; nt++) {
        const int gc = bn * 128 + wn * 64 + nt * 8 + (lane & 3) * 2;
        float2 bv = make_float2(0.f, 0.f);
        if (bias) bv = *(const float2*)(bias + gc);
        #pragma unroll
        for (int mt = 0; mt < 2; mt++) {
            const int r0 = bm * 128 + wm * 32 + mt * 16 + (lane >> 2);
            #pragma unroll
            for (int half = 0; half < 2; half++) {
                const int grow = r0 + half * 8;
                float v0 = acc[mt][nt][2 * half + 0] * scale + bv.x;
                float v1 = acc[mt][nt][2 * half + 1] * scale + bv.y;
                if (emode == 0) {
                    const long long gp = coff + (long long)grow * ldc + gc;
                    if (Cf) *(float2*)(Cf + gp) = make_float2(v0, v1);
                    if (Csh) {
                        uint2 s = split2(v0, v1);
                        *(uint32_t*)(Csh + gp) = s.x;
                        *(uint32_t*)(Csl + gp) = s.y;
                    }
                } else if (emode == 1) {
                    if (gc >= 2048) {
                        const int s = grow & (SSx - 1);
                        const int i2 = (gc - 2048) & (RRx - 1);
                        const int ii = s * 256 + (i2 >> 1);
                        float sn = g_sin[ii], cs = g_cos[ii];
                        float o0 = v0 * cs - v1 * sn;
                        float o1 = v1 * cs + v0 * sn;
                        v0 = o0; v1 = o1;
                    }
                    *(uint32_t*)(Csh + (long long)grow * ldc + gc) = h2pack(v0, v1);
                } else if (emode == 2) {
                    if (gc < 2048)
                        *(uint32_t*)(Csh + (long long)grow * 2048 + gc) = h2pack(v0, v1);
                    else
                        *(float2*)(Cf + (long long)grow * 2048 + gc - 2048) =
                            make_float2(v0, v1);
                } else {   // emode == 3: single fp16 plane, z-scatter
                    const long long gp = coff + (long long)grow * ldc + gc;
                    *(uint32_t*)(Csh + gp) = h2pack(v0, v1);
                }
            }
        }
    }
}

// ---------- scores GEMM, piecewise q/k addressing, single-plane A and B ---------
__global__ void __launch_bounds__(256, 2) k_gemm_qk()
{
    extern __shared__ __align__(16) char smem[];
    const uint32_t sb = smem_u32(smem);
    const int tid = threadIdx.x, lane = tid & 31, wid = tid >> 5;
    const int wm = wid >> 1, wn = wid & 1;
    const int z = blockIdx.z, bm = blockIdx.y, bn = blockIdx.x;
    const int b = z >> 4, h = z & 15;
    const long long gRow0 = (long long)b * SSx + bm * 128;
    const long long kRow0 = (long long)b * SSx + bn * 128;
    const int nCh = QKD / 32;    // 20

    auto issue = [&](int c) {
        if (c < nCh) {
            const uint32_t sdst = sb + (c & 1) * STG_L;
            const int row = (tid >> 2);
            const int col16 = (tid & 3);
            const int colA = (c < 4) ? (h * VHDx + c * 32)
                                     : (2048 + h * RRx + (c - 4) * 32);
            #pragma unroll
            for (int p = 0; p < 4; p++) {       // planes: A (pl 0), B (pl 1)
                const int pl = p >> 1;
                const int r = (p & 1) * 64 + row;
                uint32_t dst = sdst + pl * 2 * PLA_L + r * PITCH + col16 * 16;
                if (pl == 0) {
                    CP16(dst, g_quh + (gRow0 + r) * NQ + colA + col16 * 8);
                } else {
                    if (c < 4)
                        CP16(dst, g_kch + (kRow0 + r) * UPx + h * VHDx + c * 32 + col16 * 8);
                    else
                        CP16(dst, g_krh + (kRow0 + r) * RRx + (c - 4) * 32 + col16 * 8);
                }
            }
            CP_COMMIT();
        }
    };

    float acc[2][8][4];
    #pragma unroll
    for (int i = 0; i < 2; i++)
        #pragma unroll
        for (int j = 0; j < 8; j++)
            #pragma unroll
            for (int r = 0; r < 4; r++) acc[i][j][r] = 0.f;

    issue(0);

    for (int c = 0; c < nCh; c++) {
        CP_WAIT0();
        __syncthreads();
        issue(c + 1);

        const uint32_t sbuf = sb + (c & 1) * STG_L;
        #pragma unroll
        for (int k16 = 0; k16 < 2; k16++) {
            uint32_t af[2][4];
            uint32_t abase = sbuf + (wm * 32 + (lane & 15)) * PITCH
                           + (k16 * 16 + (lane >> 4) * 8) * 2;
            #pragma unroll
            for (int mt = 0; mt < 2; mt++)
                ldm4(af[mt], abase + mt * 16 * PITCH);
            uint32_t bbase = sbuf + 2 * PLA_L
                + (wn * 64 + (lane & 7) + ((lane >> 4) << 3)) * PITCH
                + (k16 * 16 + ((lane >> 3) & 1) * 8) * 2;
            #pragma unroll
            for (int nb = 0; nb < 4; nb++) {
                uint32_t bh[4];
                ldm4(bh, bbase + nb * 16 * PITCH);
                #pragma unroll
                for (int hf = 0; hf < 2; hf++) {
                    const int nt = nb * 2 + hf;
                    #pragma unroll
                    for (int mt = 0; mt < 2; mt++)
                        mma16816(acc[mt][nt], af[mt], &bh[2 * hf]);
                }
            }
        }
    }

    float* C = g_sc + (size_t)z * SSx * SSx;
    #pragma unroll
    for (int nt = 0; nt < 8; nt++) {
        const int gc = bn * 128 + wn * 64 + nt * 8 + (lane & 3) * 2;
        #pragma unroll
        for (int mt = 0; mt < 2; mt++) {
            const int r0 = bm * 128 + wm * 32 + mt * 16 + (lane >> 2);
            #pragma unroll
            for (int half = 0; half < 2; half++) {
                const long long gp = (long long)(r0 + half * 8) * SSx + gc;
                *(float2*)(C + gp) = make_float2(
                    acc[mt][nt][2 * half + 0] * INV_SCALE,
                    acc[mt][nt][2 * half + 1] * INV_SCALE);
            }
        }
    }
}

__global__ void k_half_x(const float* __restrict__ s, uint16_t* __restrict__ dh, int n2) {
    int i = blockIdx.x * 256 + threadIdx.x;
    if (i < n2) {
        float2 v = *(const float2*)(s + 2 * i);
        *(uint32_t*)(dh + 2 * i) = h2pack(v.x, v.y);
    }
}
__global__ void k_trsp(const float* __restrict__ W, uint16_t* __restrict__ Wth,
                       int Kd, int Nd) {
    __shared__ float t[32][33];
    int n0 = blockIdx.x * 32, k0 = blockIdx.y * 32;
    int tx = threadIdx.x, ty = threadIdx.y;
    #pragma unroll
    for (int i = 0; i < 32; i += 8)
        t[ty + i][tx] = W[(size_t)(k0 + ty + i) * Nd + n0 + tx];
    __syncthreads();
    #pragma unroll
    for (int i = 0; i < 32; i += 8)
        Wth[(size_t)(n0 + ty + i) * Kd + k0 + tx] =
            __half_as_ushort(__float2half_rn(t[tx][ty + i]));
}
__global__ void k_cat3(float* dst, const float* a, const float* b, const float* c,
                       int na, int nb, int nc) {
    int i = blockIdx.x * 256 + threadIdx.x;
    if (i < na) dst[i] = a[i];
    else if (i < na + nb) dst[i] = b[i - na];
    else if (i < na + nb + nc) dst[i] = c[i - na - nb];
}
__global__ void k_cat2(float* dst, const float* a, const float* b, int na, int nb) {
    int i = blockIdx.x * 256 + threadIdx.x;
    if (i < na) dst[i] = a[i];
    else if (i < na + nb) dst[i] = b[i - na];
}
__global__ void k_table() {
    int idx = blockIdx.x * 256 + threadIdx.x;
    int s = idx >> 8, i = idx & 255;
    float dv = expf((float)(2 * i) * (-9.210340371976184f / (float)RRx));
    float sn, cs; sincosf((float)s * dv, &sn, &cs);
    g_sin[idx] = sn; g_cos[idx] = cs;
}
__global__ void k_rope_k() {
    int idx = blockIdx.x * 256 + threadIdx.x;
    int i = idx & 255, row = idx >> 8, s = row & (SSx - 1);
    size_t o = (size_t)row * NDOWN + 1024 + 2 * i;
    float vx = join1(g_d0sh[o],     g_d0sl[o]);
    float vy = join1(g_d0sh[o + 1], g_d0sl[o + 1]);
    float sn = g_sin[s * 256 + i], cs = g_cos[s * 256 + i];
    *(uint32_t*)(g_krh + (size_t)row * RRx + 2 * i) =
        h2pack(vx * cs - vy * sn, vy * cs + vx * sn);
}
__global__ void k_vt() {
    __shared__ float t[32][33];
    int z = blockIdx.z, b = z >> 4, h = z & 15;
    int s0 = blockIdx.x * 32, d0 = blockIdx.y * 32;
    int tx = threadIdx.x, ty = threadIdx.y;
    #pragma unroll
    for (int i = 0; i < 32; i += 8)
        t[ty + i][tx] = g_vf[(size_t)(b * SSx + s0 + ty + i) * UPx + h * VHDx + d0 + tx];
    __syncthreads();
    #pragma unroll
    for (int i = 0; i < 32; i += 8)
        g_vtsh[(size_t)z * (VHDx * SSx) + (size_t)(d0 + ty + i) * SSx + s0 + tx] =
            __half_as_ushort(__float2half_rn(t[tx][ty + i]));
}
__global__ void __launch_bounds__(128) k_softmax() {
    size_t row = blockIdx.x;
    const float* p = g_sc + row * SSx;
    int t = threadIdx.x;
    float4 v = ((const float4*)p)[t];
    float m = fmaxf(fmaxf(v.x, v.y), fmaxf(v.z, v.w));
    #pragma unroll
    for (int o = 16; o; o >>= 1) m = fmaxf(m, __shfl_xor_sync(0xffffffffu, m, o));
    __shared__ float rm[4], rs[4];
    if ((t & 31) == 0) rm[t >> 5] = m;
    __syncthreads();
    m = fmaxf(fmaxf(rm[0], rm[1]), fmaxf(rm[2], rm[3]));
    v.x = __expf(v.x - m); v.y = __expf(v.y - m);
    v.z = __expf(v.z - m); v.w = __expf(v.w - m);
    float s = v.x + v.y + v.z + v.w;
    #pragma unroll
    for (int o = 16; o; o >>= 1) s += __shfl_xor_sync(0xffffffffu, s, o);
    if ((t & 31) == 0) rs[t >> 5] = s;
    __syncthreads();
    s = rs[0] + rs[1] + rs[2] + rs[3];
    float inv = 1.f / s;
    *(uint2*)(g_psh + row * SSx + t * 4) =
        make_uint2(h2pack(v.x * inv, v.y * inv), h2pack(v.z * inv, v.w * inv));
}

extern "C" void kernel_launch(void* const* d_in, const int* in_sizes, int n_in,
                              void* d_out, int out_size)
{
    const float* X    = (const float*)d_in[0];
    const float* Wdq  = (const float*)d_in[1];
    const float* bdq  = (const float*)d_in[2];
    const float* Wdkv = (const float*)d_in[3];
    const float* bdkv = (const float*)d_in[4];
    const float* Wuq  = (const float*)d_in[5];
    const float* buq  = (const float*)d_in[6];
    const float* Wuk  = (const float*)d_in[7];
    const float* buk  = (const float*)d_in[8];
    const float* Wuv  = (const float*)d_in[9];
    const float* buv  = (const float*)d_in[10];
    const float* Wqr  = (const float*)d_in[11];
    const float* bqr  = (const float*)d_in[12];
    const float* Wkr  = (const float*)d_in[13];
    const float* bkr  = (const float*)d_in[14];
    const float* Wfc  = (const float*)d_in[15];
    const float* bfc  = (const float*)d_in[16];
    float* out = (float*)d_out;

    cudaFuncSetAttribute(k_gemm, cudaFuncAttributeMaxDynamicSharedMemorySize, SMEMB);
    cudaFuncSetAttribute(k_gemm_qk, cudaFuncAttributeMaxDynamicSharedMemorySize, SMEMB);

    #define SYM(v, g) void* v; cudaGetSymbolAddress(&v, g)
    SYM(p_xh, g_xh);
    SYM(p_wdth, g_wdth); SYM(p_bd, g_bd);
    SYM(p_wqth, g_wqth); SYM(p_wkvth, g_wkvth);
    SYM(p_bq, g_bq); SYM(p_bkv, g_bkv);
    SYM(p_wfcth, g_wfcth);
    SYM(p_d0sh, g_d0sh); SYM(p_d0sl, g_d0sl);
    SYM(p_quh, g_quh);
    SYM(p_kch, g_kch); SYM(p_vf, g_vf);
    SYM(p_sc, g_sc); SYM(p_psh, g_psh);
    SYM(p_vtsh, g_vtsh);
    SYM(p_ofsh, g_ofsh);
    #undef SYM

    dim3 tb(32, 8);
    k_table<<<SSx, 256>>>();
    k_half_x<<<(MROWS * DDx / 2) / 256, 256>>>(X, (uint16_t*)p_xh, MROWS * DDx / 2);
    k_trsp<<<dim3(16, 64), tb>>>(Wdq,  (uint16_t*)p_wdth, 2048, 512);
    k_trsp<<<dim3(16, 64), tb>>>(Wdkv, (uint16_t*)p_wdth + (size_t)512 * 2048, 2048, 512);
    k_trsp<<<dim3(16, 64), tb>>>(Wkr,  (uint16_t*)p_wdth + (size_t)1024 * 2048, 2048, 512);
    k_trsp<<<dim3(64, 16), tb>>>(Wuq, (uint16_t*)p_wqth, 512, 2048);
    k_trsp<<<dim3(256, 16), tb>>>(Wqr, (uint16_t*)p_wqth + (size_t)UPx * 512, 512, 8192);
    k_trsp<<<dim3(64, 16), tb>>>(Wuk, (uint16_t*)p_wkvth, 512, 2048);
    k_trsp<<<dim3(64, 16), tb>>>(Wuv, (uint16_t*)p_wkvth + (size_t)UPx * 512, 512, 2048);
    k_trsp<<<dim3(64, 64), tb>>>(Wfc, (uint16_t*)p_wfcth, 2048, 2048);
    k_cat3<<<(NDOWN + 255) / 256, 256>>>((float*)p_bd, bdq, bdkv, bkr, 512, 512, 512);
    k_cat2<<<(NQ + 255) / 256, 256>>>((float*)p_bq, buq, bqr, UPx, RRx * HHx);
    k_cat2<<<(NKV + 255) / 256, 256>>>((float*)p_bkv, buk, buv, UPx, UPx);

    // fused down-proj: M=4096, N=1536, K=2048, single-plane X A-side
    k_gemm<<<dim3(12, 32, 1), 256, SMEMB>>>(
        (uint16_t*)p_xh, (uint16_t*)p_xh, DDx, 0,
        (uint16_t*)p_wdth, DDx, 0,
        nullptr, (uint16_t*)p_d0sh, (uint16_t*)p_d0sl, NDOWN, 0, 0,
        (float*)p_bd, 1.f, DDx, 0, 0);

    // merged q-side up-proj with fused rope, single-plane q out: M=4096, N=10240, K=512
    k_gemm<<<dim3(80, 32, 1), 256, SMEMB>>>(
        (uint16_t*)p_d0sh, (uint16_t*)p_d0sl, NDOWN, 0,
        (uint16_t*)p_wqth, DWN, 0,
        nullptr, (uint16_t*)p_quh, nullptr, NQ, 0, 0,
        (float*)p_bq, 1.f, DWN, 1, 1);
    // merged kv-side up-proj: K content fp16 + V fp32: M=4096, N=4096, K=512
    k_gemm<<<dim3(32, 32, 1), 256, SMEMB>>>(
        (uint16_t*)p_d0sh + 512, (uint16_t*)p_d0sl + 512, NDOWN, 0,
        (uint16_t*)p_wkvth, DWN, 0,
        (float*)p_vf, (uint16_t*)p_kch, nullptr, 2048, 0, 0,
        (float*)p_bkv, 1.f, DWN, 2, 1);

    k_rope_k<<<MROWS, 256>>>();
    k_vt<<<dim3(16, 4, ZBx), tb>>>();

    // scores: per z M=512, N=512, K=640, single-plane q and k
    k_gemm_qk<<<dim3(4, 4, ZBx), 256, SMEMB>>>();

    k_softmax<<<ZBx * SSx, 128>>>();

    // PV: per z M=512, N=128, K=512, single-plane A (probs), single-plane O out
    k_gemm<<<dim3(1, 4, ZBx), 256, SMEMB>>>(
        (uint16_t*)p_psh, (uint16_t*)p_psh, SSx, (long long)SSx * SSx,
        (uint16_t*)p_vtsh, SSx, (long long)VHDx * SSx,
        nullptr, (uint16_t*)p_ofsh, nullptr, UPx,
        (long long)SSx * UPx, (long long)VHDx,
        nullptr, 1.f, SSx, 3, 0);

    // final: M=4096, N=2048, K=2048, single-plane O A-side -> out fp32
    k_gemm<<<dim3(16, 32, 1), 256, SMEMB>>>(
        (uint16_t*)p_ofsh, (uint16_t*)p_ofsh, UPx, 0,
        (uint16_t*)p_wfcth, DDx, 0,
        out, nullptr, nullptr, DDx, 0, 0, bfc, 1.f, DDx, 0, 0);
}

// round 15
// speedup vs baseline: 1.2532x; 1.0483x over previous
#include <cuda_runtime.h>
#include <cuda_fp16.h>
#include <cstdint>
#include <math.h>

#define BBx   8
#define SSx   512
#define DDx   2048
#define HHx   16
#define DWN   512
#define UPx   2048
#define RRx   512
#define VHDx  128
#define MROWS (BBx*SSx)
#define ZBx   (BBx*HHx)
#define QKD   (VHDx+RRx)
#define NDOWN (DWN*3)
#define NQ    (UPx + RRx*HHx)     // 10240  (qc | qr)
#define NKV   (UPx + UPx)         // 4096   (kc | vc)
#define INV_SCALE 0.0294627825494394758f

// fp16 planes; all activation tensors now single-plane fp16.
__device__ uint16_t g_xh  [(size_t)MROWS*DDx];
__device__ uint16_t g_wdth[(size_t)NDOWN*DDx];      // B
__device__ float    g_bd  [NDOWN];
__device__ uint16_t g_wqth[(size_t)NQ*DWN];         // B
__device__ uint16_t g_wkvth[(size_t)NKV*DWN];       // B
__device__ float    g_bq  [NQ];
__device__ float    g_bkv [NKV];
__device__ uint16_t g_wfcth[(size_t)DDx*DDx];       // B
__device__ uint16_t g_d0h [(size_t)MROWS*NDOWN];    // latents single plane
__device__ uint16_t g_quh [(size_t)MROWS*NQ];       // q roped single plane
__device__ uint16_t g_kch [(size_t)MROWS*UPx];
__device__ float    g_vf  [(size_t)MROWS*UPx];
__device__ uint16_t g_krh [(size_t)MROWS*RRx];
__device__ float    g_sc  [(size_t)ZBx*SSx*SSx];
__device__ uint16_t g_psh [(size_t)ZBx*SSx*SSx];    // probs single plane
__device__ uint16_t g_vtsh[(size_t)ZBx*VHDx*SSx];   // B
__device__ uint16_t g_ofsh[(size_t)MROWS*UPx];      // O single plane
__device__ float    g_sin [SSx*(RRx/2)];
__device__ float    g_cos [SSx*(RRx/2)];

__device__ __forceinline__ uint32_t smem_u32(const void* p) {
    uint32_t a;
    asm("{ .reg .u64 t; cvta.to.shared.u64 t, %1; cvt.u32.u64 %0, t; }" : "=r"(a) : "l"(p));
    return a;
}
__device__ __forceinline__ void split1(float v, uint16_t& h, uint16_t& l) {
    __half hb = __float2half_rn(v);
    __half lb = __float2half_rn(v - __half2float(hb));
    h = __half_as_ushort(hb); l = __half_as_ushort(lb);
}
__device__ __forceinline__ uint2 split2(float a, float b) {
    uint16_t ah, al, bh, bl; split1(a, ah, al); split1(b, bh, bl);
    return make_uint2((uint32_t)ah | ((uint32_t)bh << 16),
                      (uint32_t)al | ((uint32_t)bl << 16));
}
__device__ __forceinline__ uint32_t h2pack(float a, float b) {
    __half2 h = __floats2half2_rn(a, b);
    return *(uint32_t*)&h;
}
__device__ __forceinline__ void ldm4(uint32_t* r, uint32_t addr) {
    asm volatile("ldmatrix.sync.aligned.m8n8.x4.shared.b16 {%0,%1,%2,%3}, [%4];"
        : "=r"(r[0]), "=r"(r[1]), "=r"(r[2]), "=r"(r[3]) : "r"(addr));
}
__device__ __forceinline__ void mma16816(float* c, const uint32_t* a, const uint32_t* b) {
    asm volatile("mma.sync.aligned.m16n8k16.row.col.f32.f16.f16.f32 "
        "{%0,%1,%2,%3}, {%4,%5,%6,%7}, {%8,%9}, {%0,%1,%2,%3};"
        : "+f"(c[0]), "+f"(c[1]), "+f"(c[2]), "+f"(c[3])
        : "r"(a[0]), "r"(a[1]), "r"(a[2]), "r"(a[3]), "r"(b[0]), "r"(b[1]));
}
#define CP16(dst, src) \
    asm volatile("cp.async.cg.shared.global [%0], [%1], 16;" :: "r"(dst), "l"(src))
#define CP_COMMIT() asm volatile("cp.async.commit_group;" ::: "memory")
#define CP_WAIT0()  asm volatile("cp.async.wait_group 0;" ::: "memory")

#define PITCH  80
#define PLA_L  (128*PITCH)
#define STG_L  (3*PLA_L)          // 30720 per stage
#define SMEMB  (2*STG_L)          // 61440 -> 2 CTAs/SM

// ------------------ generic GEMM: C = scale*(A @ B^T) + bias --------------------
// emode 0: std (fp32 Cf and/or split Csh/Csl, z-scatter)
// emode 1: q-up rope + single fp16 plane store
// emode 2: kv-up (K fp16 / V fp32)
// emode 3: single fp16 plane store to Csh with z-scatter
// aSplit: 1 = A hi+lo planes (2 mmas); 0 = A single plane (1 mma)
__global__ void __launch_bounds__(256, 2) k_gemm(
    const uint16_t* __restrict__ Ah, const uint16_t* __restrict__ Al, int lda, long long aB,
    const uint16_t* __restrict__ Bh, int ldb, long long bB,
    float* Cf, uint16_t* Csh, uint16_t* Csl, int ldc, long long cO, long long cI,
    const float* __restrict__ bias, float scale, int K, int emode, int aSplit)
{
    extern __shared__ __align__(16) char smem[];
    const uint32_t sb = smem_u32(smem);
    const int tid = threadIdx.x, lane = tid & 31, wid = tid >> 5;
    const int wm = wid >> 1, wn = wid & 1;     // 4m x 2n
    const int z = blockIdx.z, bm = blockIdx.y, bn = blockIdx.x;

    const uint16_t* pb0 = Ah + (size_t)z * aB + (size_t)bm * 128 * lda;
    const uint16_t* pb1 = Al + (size_t)z * aB + (size_t)bm * 128 * lda;
    const uint16_t* pb2 = Bh + (size_t)z * bB + (size_t)bn * 128 * ldb;
    const int nCh = K / 32;

    auto issue = [&](int c) {
        if (c < nCh) {
            const int kc = c * 32;
            const uint32_t sdst = sb + (c & 1) * STG_L;
            const int row = (tid >> 2);
            const int col16 = (tid & 3);
            #pragma unroll
            for (int p = 0; p < 6; p++) {
                const int pl = p >> 1;
                if (pl == 1 && !aSplit) continue;
                const int r = (p & 1) * 64 + row;
                const uint16_t* src = (pl == 0 ? pb0 : pl == 1 ? pb1 : pb2);
                const int ld = (pl < 2) ? lda : ldb;
                CP16(sdst + pl * PLA_L + r * PITCH + col16 * 16,
                     src + (size_t)r * ld + kc + col16 * 8);
            }
            CP_COMMIT();
        }
    };

    float acc[2][8][4];
    #pragma unroll
    for (int i = 0; i < 2; i++)
        #pragma unroll
        for (int j = 0; j < 8; j++)
            #pragma unroll
            for (int r = 0; r < 4; r++) acc[i][j][r] = 0.f;

    issue(0);

    for (int c = 0; c < nCh; c++) {
        CP_WAIT0();
        __syncthreads();
        issue(c + 1);

        const uint32_t sbuf = sb + (c & 1) * STG_L;
        #pragma unroll
        for (int k16 = 0; k16 < 2; k16++) {
            uint32_t af[2][2][4];
            uint32_t abase = sbuf + (wm * 32 + (lane & 15)) * PITCH
                           + (k16 * 16 + (lane >> 4) * 8) * 2;
            #pragma unroll
            for (int mt = 0; mt < 2; mt++) {
                ldm4(af[0][mt], abase + mt * 16 * PITCH);
                if (aSplit) ldm4(af[1][mt], abase + PLA_L + mt * 16 * PITCH);
            }
            uint32_t bbase = sbuf + 2 * PLA_L
                + (wn * 64 + (lane & 7) + ((lane >> 4) << 3)) * PITCH
                + (k16 * 16 + ((lane >> 3) & 1) * 8) * 2;
            #pragma unroll
            for (int nb = 0; nb < 4; nb++) {
                uint32_t bh[4];
                ldm4(bh, bbase + nb * 16 * PITCH);
                #pragma unroll
                for (int hf = 0; hf < 2; hf++) {
                    const int nt = nb * 2 + hf;
                    #pragma unroll
                    for (int mt = 0; mt < 2; mt++) {
                        mma16816(acc[mt][nt], af[0][mt], &bh[2 * hf]);
                        if (aSplit) mma16816(acc[mt][nt], af[1][mt], &bh[2 * hf]);
                    }
                }
            }
        }
    }

    const long long coff = (long long)(z >> 4) * cO + (long long)(z & 15) * cI;
    #pragma unroll
    for (int nt = 0; nt < 8; nt++) {
        const int gc = bn * 128 + wn * 64 + nt * 8 + (lane & 3) * 2;
        float2 bv = make_float2(0.f, 0.f);
        if (bias) bv = *(const float2*)(bias + gc);
        #pragma unroll
        for (int mt = 0; mt < 2; mt++) {
            const int r0 = bm * 128 + wm * 32 + mt * 16 + (lane >> 2);
            #pragma unroll
            for (int half = 0; half < 2; half++) {
                const int grow = r0 + half * 8;
                float v0 = acc[mt][nt][2 * half + 0] * scale + bv.x;
                float v1 = acc[mt][nt][2 * half + 1] * scale + bv.y;
                if (emode == 0) {
                    const long long gp = coff + (long long)grow * ldc + gc;
                    if (Cf) *(float2*)(Cf + gp) = make_float2(v0, v1);
                    if (Csh) {
                        uint2 s = split2(v0, v1);
                        *(uint32_t*)(Csh + gp) = s.x;
                        *(uint32_t*)(Csl + gp) = s.y;
                    }
                } else if (emode == 1) {
                    if (gc >= 2048) {
                        const int s = grow & (SSx - 1);
                        const int i2 = (gc - 2048) & (RRx - 1);
                        const int ii = s * 256 + (i2 >> 1);
                        float sn = g_sin[ii], cs = g_cos[ii];
                        float o0 = v0 * cs - v1 * sn;
                        float o1 = v1 * cs + v0 * sn;
                        v0 = o0; v1 = o1;
                    }
                    *(uint32_t*)(Csh + (long long)grow * ldc + gc) = h2pack(v0, v1);
                } else if (emode == 2) {
                    if (gc < 2048)
                        *(uint32_t*)(Csh + (long long)grow * 2048 + gc) = h2pack(v0, v1);
                    else
                        *(float2*)(Cf + (long long)grow * 2048 + gc - 2048) =
                            make_float2(v0, v1);
                } else {   // emode == 3: single fp16 plane, z-scatter
                    const long long gp = coff + (long long)grow * ldc + gc;
                    *(uint32_t*)(Csh + gp) = h2pack(v0, v1);
                }
            }
        }
    }
}

// ---------- scores GEMM, piecewise q/k addressing, single-plane A and B ---------
__global__ void __launch_bounds__(256, 2) k_gemm_qk()
{
    extern __shared__ __align__(16) char smem[];
    const uint32_t sb = smem_u32(smem);
    const int tid = threadIdx.x, lane = tid & 31, wid = tid >> 5;
    const int wm = wid >> 1, wn = wid & 1;
    const int z = blockIdx.z, bm = blockIdx.y, bn = blockIdx.x;
    const int b = z >> 4, h = z & 15;
    const long long gRow0 = (long long)b * SSx + bm * 128;
    const long long kRow0 = (long long)b * SSx + bn * 128;
    const int nCh = QKD / 32;    // 20

    auto issue = [&](int c) {
        if (c < nCh) {
            const uint32_t sdst = sb + (c & 1) * STG_L;
            const int row = (tid >> 2);
            const int col16 = (tid & 3);
            const int colA = (c < 4) ? (h * VHDx + c * 32)
                                     : (2048 + h * RRx + (c - 4) * 32);
            #pragma unroll
            for (int p = 0; p < 4; p++) {
                const int pl = p >> 1;
                const int r = (p & 1) * 64 + row;
                uint32_t dst = sdst + pl * 2 * PLA_L + r * PITCH + col16 * 16;
                if (pl == 0) {
                    CP16(dst, g_quh + (gRow0 + r) * NQ + colA + col16 * 8);
                } else {
                    if (c < 4)
                        CP16(dst, g_kch + (kRow0 + r) * UPx + h * VHDx + c * 32 + col16 * 8);
                    else
                        CP16(dst, g_krh + (kRow0 + r) * RRx + (c - 4) * 32 + col16 * 8);
                }
            }
            CP_COMMIT();
        }
    };

    float acc[2][8][4];
    #pragma unroll
    for (int i = 0; i < 2; i++)
        #pragma unroll
        for (int j = 0; j < 8; j++)
            #pragma unroll
            for (int r = 0; r < 4; r++) acc[i][j][r] = 0.f;

    issue(0);

    for (int c = 0; c < nCh; c++) {
        CP_WAIT0();
        __syncthreads();
        issue(c + 1);

        const uint32_t sbuf = sb + (c & 1) * STG_L;
        #pragma unroll
        for (int k16 = 0; k16 < 2; k16++) {
            uint32_t af[2][4];
            uint32_t abase = sbuf + (wm * 32 + (lane & 15)) * PITCH
                           + (k16 * 16 + (lane >> 4) * 8) * 2;
            #pragma unroll
            for (int mt = 0; mt < 2; mt++)
                ldm4(af[mt], abase + mt * 16 * PITCH);
            uint32_t bbase = sbuf + 2 * PLA_L
                + (wn * 64 + (lane & 7) + ((lane >> 4) << 3)) * PITCH
                + (k16 * 16 + ((lane >> 3) & 1) * 8) * 2;
            #pragma unroll
            for (int nb = 0; nb < 4; nb++) {
                uint32_t bh[4];
                ldm4(bh, bbase + nb * 16 * PITCH);
                #pragma unroll
                for (int hf = 0; hf < 2; hf++) {
                    const int nt = nb * 2 + hf;
                    #pragma unroll
                    for (int mt = 0; mt < 2; mt++)
                        mma16816(acc[mt][nt], af[mt], &bh[2 * hf]);
                }
            }
        }
    }

    float* C = g_sc + (size_t)z * SSx * SSx;
    #pragma unroll
    for (int nt = 0; nt < 8; nt++) {
        const int gc = bn * 128 + wn * 64 + nt * 8 + (lane & 3) * 2;
        #pragma unroll
        for (int mt = 0; mt < 2; mt++) {
            const int r0 = bm * 128 + wm * 32 + mt * 16 + (lane >> 2);
            #pragma unroll
            for (int half = 0; half < 2; half++) {
                const long long gp = (long long)(r0 + half * 8) * SSx + gc;
                *(float2*)(C + gp) = make_float2(
                    acc[mt][nt][2 * half + 0] * INV_SCALE,
                    acc[mt][nt][2 * half + 1] * INV_SCALE);
            }
        }
    }
}

__global__ void k_half_x(const float* __restrict__ s, uint16_t* __restrict__ dh, int n2) {
    int i = blockIdx.x * 256 + threadIdx.x;
    if (i < n2) {
        float2 v = *(const float2*)(s + 2 * i);
        *(uint32_t*)(dh + 2 * i) = h2pack(v.x, v.y);
    }
}
__global__ void k_trsp(const float* __restrict__ W, uint16_t* __restrict__ Wth,
                       int Kd, int Nd) {
    __shared__ float t[32][33];
    int n0 = blockIdx.x * 32, k0 = blockIdx.y * 32;
    int tx = threadIdx.x, ty = threadIdx.y;
    #pragma unroll
    for (int i = 0; i < 32; i += 8)
        t[ty + i][tx] = W[(size_t)(k0 + ty + i) * Nd + n0 + tx];
    __syncthreads();
    #pragma unroll
    for (int i = 0; i < 32; i += 8)
        Wth[(size_t)(n0 + ty + i) * Kd + k0 + tx] =
            __half_as_ushort(__float2half_rn(t[tx][ty + i]));
}
__global__ void k_cat3(float* dst, const float* a, const float* b, const float* c,
                       int na, int nb, int nc) {
    int i = blockIdx.x * 256 + threadIdx.x;
    if (i < na) dst[i] = a[i];
    else if (i < na + nb) dst[i] = b[i - na];
    else if (i < na + nb + nc) dst[i] = c[i - na - nb];
}
__global__ void k_cat2(float* dst, const float* a, const float* b, int na, int nb) {
    int i = blockIdx.x * 256 + threadIdx.x;
    if (i < na) dst[i] = a[i];
    else if (i < na + nb) dst[i] = b[i - na];
}
__global__ void k_table() {
    int idx = blockIdx.x * 256 + threadIdx.x;
    int s = idx >> 8, i = idx & 255;
    float dv = expf((float)(2 * i) * (-9.210340371976184f / (float)RRx));
    float sn, cs; sincosf((float)s * dv, &sn, &cs);
    g_sin[idx] = sn; g_cos[idx] = cs;
}
__global__ void k_rope_k() {
    int idx = blockIdx.x * 256 + threadIdx.x;
    int i = idx & 255, row = idx >> 8, s = row & (SSx - 1);
    size_t o = (size_t)row * NDOWN + 1024 + 2 * i;
    float vx = __half2float(__ushort_as_half(g_d0h[o]));
    float vy = __half2float(__ushort_as_half(g_d0h[o + 1]));
    float sn = g_sin[s * 256 + i], cs = g_cos[s * 256 + i];
    *(uint32_t*)(g_krh + (size_t)row * RRx + 2 * i) =
        h2pack(vx * cs - vy * sn, vy * cs + vx * sn);
}
__global__ void k_vt() {
    __shared__ float t[32][33];
    int z = blockIdx.z, b = z >> 4, h = z & 15;
    int s0 = blockIdx.x * 32, d0 = blockIdx.y * 32;
    int tx = threadIdx.x, ty = threadIdx.y;
    #pragma unroll
    for (int i = 0; i < 32; i += 8)
        t[ty + i][tx] = g_vf[(size_t)(b * SSx + s0 + ty + i) * UPx + h * VHDx + d0 + tx];
    __syncthreads();
    #pragma unroll
    for (int i = 0; i < 32; i += 8)
        g_vtsh[(size_t)z * (VHDx * SSx) + (size_t)(d0 + ty + i) * SSx + s0 + tx] =
            __half_as_ushort(__float2half_rn(t[tx][ty + i]));
}
__global__ void __launch_bounds__(128) k_softmax() {
    size_t row = blockIdx.x;
    const float* p = g_sc + row * SSx;
    int t = threadIdx.x;
    float4 v = ((const float4*)p)[t];
    float m = fmaxf(fmaxf(v.x, v.y), fmaxf(v.z, v.w));
    #pragma unroll
    for (int o = 16; o; o >>= 1) m = fmaxf(m, __shfl_xor_sync(0xffffffffu, m, o));
    __shared__ float rm[4], rs[4];
    if ((t & 31) == 0) rm[t >> 5] = m;
    __syncthreads();
    m = fmaxf(fmaxf(rm[0], rm[1]), fmaxf(rm[2], rm[3]));
    v.x = __expf(v.x - m); v.y = __expf(v.y - m);
    v.z = __expf(v.z - m); v.w = __expf(v.w - m);
    float s = v.x + v.y + v.z + v.w;
    #pragma unroll
    for (int o = 16; o; o >>= 1) s += __shfl_xor_sync(0xffffffffu, s, o);
    if ((t & 31) == 0) rs[t >> 5] = s;
    __syncthreads();
    s = rs[0] + rs[1] + rs[2] + rs[3];
    float inv = 1.f / s;
    *(uint2*)(g_psh + row * SSx + t * 4) =
        make_uint2(h2pack(v.x * inv, v.y * inv), h2pack(v.z * inv, v.w * inv));
}

extern "C" void kernel_launch(void* const* d_in, const int* in_sizes, int n_in,
                              void* d_out, int out_size)
{
    const float* X    = (const float*)d_in[0];
    const float* Wdq  = (const float*)d_in[1];
    const float* bdq  = (const float*)d_in[2];
    const float* Wdkv = (const float*)d_in[3];
    const float* bdkv = (const float*)d_in[4];
    const float* Wuq  = (const float*)d_in[5];
    const float* buq  = (const float*)d_in[6];
    const float* Wuk  = (const float*)d_in[7];
    const float* buk  = (const float*)d_in[8];
    const float* Wuv  = (const float*)d_in[9];
    const float* buv  = (const float*)d_in[10];
    const float* Wqr  = (const float*)d_in[11];
    const float* bqr  = (const float*)d_in[12];
    const float* Wkr  = (const float*)d_in[13];
    const float* bkr  = (const float*)d_in[14];
    const float* Wfc  = (const float*)d_in[15];
    const float* bfc  = (const float*)d_in[16];
    float* out = (float*)d_out;

    cudaFuncSetAttribute(k_gemm, cudaFuncAttributeMaxDynamicSharedMemorySize, SMEMB);
    cudaFuncSetAttribute(k_gemm_qk, cudaFuncAttributeMaxDynamicSharedMemorySize, SMEMB);

    #define SYM(v, g) void* v; cudaGetSymbolAddress(&v, g)
    SYM(p_xh, g_xh);
    SYM(p_wdth, g_wdth); SYM(p_bd, g_bd);
    SYM(p_wqth, g_wqth); SYM(p_wkvth, g_wkvth);
    SYM(p_bq, g_bq); SYM(p_bkv, g_bkv);
    SYM(p_wfcth, g_wfcth);
    SYM(p_d0h, g_d0h);
    SYM(p_quh, g_quh);
    SYM(p_kch, g_kch); SYM(p_vf, g_vf);
    SYM(p_sc, g_sc); SYM(p_psh, g_psh);
    SYM(p_vtsh, g_vtsh);
    SYM(p_ofsh, g_ofsh);
    #undef SYM

    dim3 tb(32, 8);
    k_table<<<SSx, 256>>>();
    k_half_x<<<(MROWS * DDx / 2) / 256, 256>>>(X, (uint16_t*)p_xh, MROWS * DDx / 2);
    k_trsp<<<dim3(16, 64), tb>>>(Wdq,  (uint16_t*)p_wdth, 2048, 512);
    k_trsp<<<dim3(16, 64), tb>>>(Wdkv, (uint16_t*)p_wdth + (size_t)512 * 2048, 2048, 512);
    k_trsp<<<dim3(16, 64), tb>>>(Wkr,  (uint16_t*)p_wdth + (size_t)1024 * 2048, 2048, 512);
    k_trsp<<<dim3(64, 16), tb>>>(Wuq, (uint16_t*)p_wqth, 512, 2048);
    k_trsp<<<dim3(256, 16), tb>>>(Wqr, (uint16_t*)p_wqth + (size_t)UPx * 512, 512, 8192);
    k_trsp<<<dim3(64, 16), tb>>>(Wuk, (uint16_t*)p_wkvth, 512, 2048);
    k_trsp<<<dim3(64, 16), tb>>>(Wuv, (uint16_t*)p_wkvth + (size_t)UPx * 512, 512, 2048);
    k_trsp<<<dim3(64, 64), tb>>>(Wfc, (uint16_t*)p_wfcth, 2048, 2048);
    k_cat3<<<(NDOWN + 255) / 256, 256>>>((float*)p_bd, bdq, bdkv, bkr, 512, 512, 512);
    k_cat2<<<(NQ + 255) / 256, 256>>>((float*)p_bq, buq, bqr, UPx, RRx * HHx);
    k_cat2<<<(NKV + 255) / 256, 256>>>((float*)p_bkv, buk, buv, UPx, UPx);

    // fused down-proj: M=4096, N=1536, K=2048, single-plane X in, single-plane d0 out
    k_gemm<<<dim3(12, 32, 1), 256, SMEMB>>>(
        (uint16_t*)p_xh, (uint16_t*)p_xh, DDx, 0,
        (uint16_t*)p_wdth, DDx, 0,
        nullptr, (uint16_t*)p_d0h, nullptr, NDOWN, 0, 0,
        (float*)p_bd, 1.f, DDx, 3, 0);

    // merged q-side up-proj (rope fused), single-plane in/out: M=4096, N=10240, K=512
    k_gemm<<<dim3(80, 32, 1), 256, SMEMB>>>(
        (uint16_t*)p_d0h, (uint16_t*)p_d0h, NDOWN, 0,
        (uint16_t*)p_wqth, DWN, 0,
        nullptr, (uint16_t*)p_quh, nullptr, NQ, 0, 0,
        (float*)p_bq, 1.f, DWN, 1, 0);
    // merged kv-side up-proj: K content fp16 + V fp32, single-plane A: M=4096, N=4096, K=512
    k_gemm<<<dim3(32, 32, 1), 256, SMEMB>>>(
        (uint16_t*)p_d0h + 512, (uint16_t*)p_d0h + 512, NDOWN, 0,
        (uint16_t*)p_wkvth, DWN, 0,
        (float*)p_vf, (uint16_t*)p_kch, nullptr, 2048, 0, 0,
        (float*)p_bkv, 1.f, DWN, 2, 0);

    k_rope_k<<<MROWS, 256>>>();
    k_vt<<<dim3(16, 4, ZBx), tb>>>();

    // scores: per z M=512, N=512, K=640, single-plane q and k
    k_gemm_qk<<<dim3(4, 4, ZBx), 256, SMEMB>>>();

    k_softmax<<<ZBx * SSx, 128>>>();

    // PV: per z M=512, N=128, K=512, single-plane probs, single-plane O out
    k_gemm<<<dim3(1, 4, ZBx), 256, SMEMB>>>(
        (uint16_t*)p_psh, (uint16_t*)p_psh, SSx, (long long)SSx * SSx,
        (uint16_t*)p_vtsh, SSx, (long long)VHDx * SSx,
        nullptr, (uint16_t*)p_ofsh, nullptr, UPx,
        (long long)SSx * UPx, (long long)VHDx,
        nullptr, 1.f, SSx, 3, 0);

    // final: M=4096, N=2048, K=2048, single-plane O -> out fp32
    k_gemm<<<dim3(16, 32, 1), 256, SMEMB>>>(
        (uint16_t*)p_ofsh, (uint16_t*)p_ofsh, UPx, 0,
        (uint16_t*)p_wfcth, DDx, 0,
        out, nullptr, nullptr, DDx, 0, 0, bfc, 1.f, DDx, 0, 0);
}

// round 16
// speedup vs baseline: 1.4992x; 1.1963x over previous
#include <cuda_runtime.h>
#include <cuda_fp16.h>
#include <cstdint>
#include <math.h>

#define BBx   8
#define SSx   512
#define DDx   2048
#define HHx   16
#define DWN   512
#define UPx   2048
#define RRx   512
#define VHDx  128
#define MROWS (BBx*SSx)
#define ZBx   (BBx*HHx)
#define QKD   (VHDx+RRx)
#define NDOWN (DWN*3)
#define NQ    (UPx + RRx*HHx)     // 10240  (qc | qr)
#define NKV   (UPx + UPx)         // 4096   (kc | vc)
#define INV_SCALE 0.0294627825494394758f

// all activation tensors: single-plane fp16
__device__ uint16_t g_xh  [(size_t)MROWS*DDx];
__device__ uint16_t g_wdth[(size_t)NDOWN*DDx];
__device__ float    g_bd  [NDOWN];
__device__ uint16_t g_wqth[(size_t)NQ*DWN];
__device__ uint16_t g_wkvth[(size_t)NKV*DWN];
__device__ float    g_bq  [NQ];
__device__ float    g_bkv [NKV];
__device__ uint16_t g_wfcth[(size_t)DDx*DDx];
__device__ uint16_t g_d0h [(size_t)MROWS*NDOWN];    // cq|ckv used; kr slice unused
__device__ uint16_t g_quh [(size_t)MROWS*NQ];
__device__ uint16_t g_kch [(size_t)MROWS*UPx];
__device__ float    g_vf  [(size_t)MROWS*UPx];
__device__ uint16_t g_krh [(size_t)MROWS*RRx];
__device__ uint16_t g_sch [(size_t)ZBx*SSx*SSx];    // scores fp16
__device__ uint16_t g_psh [(size_t)ZBx*SSx*SSx];
__device__ uint16_t g_vtsh[(size_t)ZBx*VHDx*SSx];
__device__ uint16_t g_ofsh[(size_t)MROWS*UPx];
__device__ float    g_sin [SSx*(RRx/2)];
__device__ float    g_cos [SSx*(RRx/2)];

__device__ __forceinline__ uint32_t smem_u32(const void* p) {
    uint32_t a;
    asm("{ .reg .u64 t; cvta.to.shared.u64 t, %1; cvt.u32.u64 %0, t; }" : "=r"(a) : "l"(p));
    return a;
}
__device__ __forceinline__ uint32_t h2pack(float a, float b) {
    __half2 h = __floats2half2_rn(a, b);
    return *(uint32_t*)&h;
}
__device__ __forceinline__ void ldm4(uint32_t* r, uint32_t addr) {
    asm volatile("ldmatrix.sync.aligned.m8n8.x4.shared.b16 {%0,%1,%2,%3}, [%4];"
        : "=r"(r[0]), "=r"(r[1]), "=r"(r[2]), "=r"(r[3]) : "r"(addr));
}
__device__ __forceinline__ void mma16816(float* c, const uint32_t* a, const uint32_t* b) {
    asm volatile("mma.sync.aligned.m16n8k16.row.col.f32.f16.f16.f32 "
        "{%0,%1,%2,%3}, {%4,%5,%6,%7}, {%8,%9}, {%0,%1,%2,%3};"
        : "+f"(c[0]), "+f"(c[1]), "+f"(c[2]), "+f"(c[3])
        : "r"(a[0]), "r"(a[1]), "r"(a[2]), "r"(a[3]), "r"(b[0]), "r"(b[1]));
}
#define CP16(dst, src) \
    asm volatile("cp.async.cg.shared.global [%0], [%1], 16;" :: "r"(dst), "l"(src))
#define CP_COMMIT() asm volatile("cp.async.commit_group;" ::: "memory")
#define CP_WAIT0()  asm volatile("cp.async.wait_group 0;" ::: "memory")

#define PITCH  80
#define PLA_L  (128*PITCH)
#define STG_L  (2*PLA_L)          // A + B planes = 20480 per stage
#define SMEMB  (2*STG_L)          // 40960 -> 2 CTAs/SM

// ------------------ generic GEMM: C = scale*(A @ B^T) + bias --------------------
// emode 0: fp32 Cf store
// emode 1: q-up rope + fp16 plane store
// emode 2: kv-up (K fp16 / V fp32)
// emode 3: fp16 plane store with z-scatter
// emode 4: down-proj (cols<1024 -> d0h fp16; cols>=1024 -> rope -> g_krh)
__global__ void __launch_bounds__(256, 2) k_gemm(
    const uint16_t* __restrict__ Ah, int lda, long long aB,
    const uint16_t* __restrict__ Bh, int ldb, long long bB,
    float* Cf, uint16_t* Csh, int ldc, long long cO, long long cI,
    const float* __restrict__ bias, float scale, int K, int emode)
{
    extern __shared__ __align__(16) char smem[];
    const uint32_t sb = smem_u32(smem);
    const int tid = threadIdx.x, lane = tid & 31, wid = tid >> 5;
    const int wm = wid >> 1, wn = wid & 1;     // 4m x 2n
    const int z = blockIdx.z, bm = blockIdx.y, bn = blockIdx.x;

    const uint16_t* pb0 = Ah + (size_t)z * aB + (size_t)bm * 128 * lda;
    const uint16_t* pb1 = Bh + (size_t)z * bB + (size_t)bn * 128 * ldb;
    const int nCh = K / 32;

    auto issue = [&](int c) {
        if (c < nCh) {
            const int kc = c * 32;
            const uint32_t sdst = sb + (c & 1) * STG_L;
            const int row = (tid >> 2);
            const int col16 = (tid & 3);
            #pragma unroll
            for (int p = 0; p < 4; p++) {
                const int pl = p >> 1;
                const int r = (p & 1) * 64 + row;
                const uint16_t* src = pl ? pb1 : pb0;
                const int ld = pl ? ldb : lda;
                CP16(sdst + pl * PLA_L + r * PITCH + col16 * 16,
                     src + (size_t)r * ld + kc + col16 * 8);
            }
            CP_COMMIT();
        }
    };

    float acc[2][8][4];
    #pragma unroll
    for (int i = 0; i < 2; i++)
        #pragma unroll
        for (int j = 0; j < 8; j++)
            #pragma unroll
            for (int r = 0; r < 4; r++) acc[i][j][r] = 0.f;

    issue(0);

    for (int c = 0; c < nCh; c++) {
        CP_WAIT0();
        __syncthreads();
        issue(c + 1);

        const uint32_t sbuf = sb + (c & 1) * STG_L;
        #pragma unroll
        for (int k16 = 0; k16 < 2; k16++) {
            uint32_t af[2][4];
            uint32_t abase = sbuf + (wm * 32 + (lane & 15)) * PITCH
                           + (k16 * 16 + (lane >> 4) * 8) * 2;
            #pragma unroll
            for (int mt = 0; mt < 2; mt++)
                ldm4(af[mt], abase + mt * 16 * PITCH);
            uint32_t bbase = sbuf + PLA_L
                + (wn * 64 + (lane & 7) + ((lane >> 4) << 3)) * PITCH
                + (k16 * 16 + ((lane >> 3) & 1) * 8) * 2;
            #pragma unroll
            for (int nb = 0; nb < 4; nb++) {
                uint32_t bh[4];
                ldm4(bh, bbase + nb * 16 * PITCH);
                #pragma unroll
                for (int hf = 0; hf < 2; hf++) {
                    const int nt = nb * 2 + hf;
                    #pragma unroll
                    for (int mt = 0; mt < 2; mt++)
                        mma16816(acc[mt][nt], af[mt], &bh[2 * hf]);
                }
            }
        }
    }

    const long long coff = (long long)(z >> 4) * cO + (long long)(z & 15) * cI;
    #pragma unroll
    for (int nt = 0; nt < 8; nt++) {
        const int gc = bn * 128 + wn * 64 + nt * 8 + (lane & 3) * 2;
        float2 bv = make_float2(0.f, 0.f);
        if (bias) bv = *(const float2*)(bias + gc);
        #pragma unroll
        for (int mt = 0; mt < 2; mt++) {
            const int r0 = bm * 128 + wm * 32 + mt * 16 + (lane >> 2);
            #pragma unroll
            for (int half = 0; half < 2; half++) {
                const int grow = r0 + half * 8;
                float v0 = acc[mt][nt][2 * half + 0] * scale + bv.x;
                float v1 = acc[mt][nt][2 * half + 1] * scale + bv.y;
                if (emode == 0) {
                    *(float2*)(Cf + coff + (long long)grow * ldc + gc) =
                        make_float2(v0, v1);
                } else if (emode == 1) {
                    if (gc >= 2048) {
                        const int s = grow & (SSx - 1);
                        const int ii = s * 256 + (((gc - 2048) & (RRx - 1)) >> 1);
                        float sn = g_sin[ii], cs = g_cos[ii];
                        float o0 = v0 * cs - v1 * sn;
                        float o1 = v1 * cs + v0 * sn;
                        v0 = o0; v1 = o1;
                    }
                    *(uint32_t*)(Csh + (long long)grow * ldc + gc) = h2pack(v0, v1);
                } else if (emode == 2) {
                    if (gc < 2048)
                        *(uint32_t*)(Csh + (long long)grow * 2048 + gc) = h2pack(v0, v1);
                    else
                        *(float2*)(Cf + (long long)grow * 2048 + gc - 2048) =
                            make_float2(v0, v1);
                } else if (emode == 3) {
                    *(uint32_t*)(Csh + coff + (long long)grow * ldc + gc) =
                        h2pack(v0, v1);
                } else {   // emode == 4: down-proj; kr cols roped straight to g_krh
                    if (gc < 1024) {
                        *(uint32_t*)(Csh + (long long)grow * ldc + gc) = h2pack(v0, v1);
                    } else {
                        const int s = grow & (SSx - 1);
                        const int i2 = gc - 1024;
                        const int ii = s * 256 + (i2 >> 1);
                        float sn = g_sin[ii], cs = g_cos[ii];
                        *(uint32_t*)(g_krh + (long long)grow * RRx + i2) =
                            h2pack(v0 * cs - v1 * sn, v1 * cs + v0 * sn);
                    }
                }
            }
        }
    }
}

// ---------- scores GEMM, piecewise q/k addressing, fp16 output ------------------
__global__ void __launch_bounds__(256, 2) k_gemm_qk()
{
    extern __shared__ __align__(16) char smem[];
    const uint32_t sb = smem_u32(smem);
    const int tid = threadIdx.x, lane = tid & 31, wid = tid >> 5;
    const int wm = wid >> 1, wn = wid & 1;
    const int z = blockIdx.z, bm = blockIdx.y, bn = blockIdx.x;
    const int b = z >> 4, h = z & 15;
    const long long gRow0 = (long long)b * SSx + bm * 128;
    const long long kRow0 = (long long)b * SSx + bn * 128;
    const int nCh = QKD / 32;    // 20

    auto issue = [&](int c) {
        if (c < nCh) {
            const uint32_t sdst = sb + (c & 1) * STG_L;
            const int row = (tid >> 2);
            const int col16 = (tid & 3);
            const int colA = (c < 4) ? (h * VHDx + c * 32)
                                     : (2048 + h * RRx + (c - 4) * 32);
            #pragma unroll
            for (int p = 0; p < 4; p++) {
                const int pl = p >> 1;
                const int r = (p & 1) * 64 + row;
                uint32_t dst = sdst + pl * PLA_L + r * PITCH + col16 * 16;
                if (pl == 0) {
                    CP16(dst, g_quh + (gRow0 + r) * NQ + colA + col16 * 8);
                } else {
                    if (c < 4)
                        CP16(dst, g_kch + (kRow0 + r) * UPx + h * VHDx + c * 32 + col16 * 8);
                    else
                        CP16(dst, g_krh + (kRow0 + r) * RRx + (c - 4) * 32 + col16 * 8);
                }
            }
            CP_COMMIT();
        }
    };

    float acc[2][8][4];
    #pragma unroll
    for (int i = 0; i < 2; i++)
        #pragma unroll
        for (int j = 0; j < 8; j++)
            #pragma unroll
            for (int r = 0; r < 4; r++) acc[i][j][r] = 0.f;

    issue(0);

    for (int c = 0; c < nCh; c++) {
        CP_WAIT0();
        __syncthreads();
        issue(c + 1);

        const uint32_t sbuf = sb + (c & 1) * STG_L;
        #pragma unroll
        for (int k16 = 0; k16 < 2; k16++) {
            uint32_t af[2][4];
            uint32_t abase = sbuf + (wm * 32 + (lane & 15)) * PITCH
                           + (k16 * 16 + (lane >> 4) * 8) * 2;
            #pragma unroll
            for (int mt = 0; mt < 2; mt++)
                ldm4(af[mt], abase + mt * 16 * PITCH);
            uint32_t bbase = sbuf + PLA_L
                + (wn * 64 + (lane & 7) + ((lane >> 4) << 3)) * PITCH
                + (k16 * 16 + ((lane >> 3) & 1) * 8) * 2;
            #pragma unroll
            for (int nb = 0; nb < 4; nb++) {
                uint32_t bh[4];
                ldm4(bh, bbase + nb * 16 * PITCH);
                #pragma unroll
                for (int hf = 0; hf < 2; hf++) {
                    const int nt = nb * 2 + hf;
                    #pragma unroll
                    for (int mt = 0; mt < 2; mt++)
                        mma16816(acc[mt][nt], af[mt], &bh[2 * hf]);
                }
            }
        }
    }

    uint16_t* C = g_sch + (size_t)z * SSx * SSx;
    #pragma unroll
    for (int nt = 0; nt < 8; nt++) {
        const int gc = bn * 128 + wn * 64 + nt * 8 + (lane & 3) * 2;
        #pragma unroll
        for (int mt = 0; mt < 2; mt++) {
            const int r0 = bm * 128 + wm * 32 + mt * 16 + (lane >> 2);
            #pragma unroll
            for (int half = 0; half < 2; half++) {
                const long long gp = (long long)(r0 + half * 8) * SSx + gc;
                *(uint32_t*)(C + gp) = h2pack(
                    acc[mt][nt][2 * half + 0] * INV_SCALE,
                    acc[mt][nt][2 * half + 1] * INV_SCALE);
            }
        }
    }
}

__global__ void k_half_x(const float* __restrict__ s, uint16_t* __restrict__ dh, int n2) {
    int i = blockIdx.x * 256 + threadIdx.x;
    if (i < n2) {
        float2 v = *(const float2*)(s + 2 * i);
        *(uint32_t*)(dh + 2 * i) = h2pack(v.x, v.y);
    }
}
__global__ void k_trsp(const float* __restrict__ W, uint16_t* __restrict__ Wth,
                       int Kd, int Nd) {
    __shared__ float t[32][33];
    int n0 = blockIdx.x * 32, k0 = blockIdx.y * 32;
    int tx = threadIdx.x, ty = threadIdx.y;
    #pragma unroll
    for (int i = 0; i < 32; i += 8)
        t[ty + i][tx] = W[(size_t)(k0 + ty + i) * Nd + n0 + tx];
    __syncthreads();
    #pragma unroll
    for (int i = 0; i < 32; i += 8)
        Wth[(size_t)(n0 + ty + i) * Kd + k0 + tx] =
            __half_as_ushort(__float2half_rn(t[tx][ty + i]));
}
__global__ void k_cat3(float* dst, const float* a, const float* b, const float* c,
                       int na, int nb, int nc) {
    int i = blockIdx.x * 256 + threadIdx.x;
    if (i < na) dst[i] = a[i];
    else if (i < na + nb) dst[i] = b[i - na];
    else if (i < na + nb + nc) dst[i] = c[i - na - nb];
}
__global__ void k_cat2(float* dst, const float* a, const float* b, int na, int nb) {
    int i = blockIdx.x * 256 + threadIdx.x;
    if (i < na) dst[i] = a[i];
    else if (i < na + nb) dst[i] = b[i - na];
}
__global__ void k_table() {
    int idx = blockIdx.x * 256 + threadIdx.x;
    int s = idx >> 8, i = idx & 255;
    float dv = expf((float)(2 * i) * (-9.210340371976184f / (float)RRx));
    float sn, cs; sincosf((float)s * dv, &sn, &cs);
    g_sin[idx] = sn; g_cos[idx] = cs;
}
__global__ void k_vt() {
    __shared__ float t[32][33];
    int z = blockIdx.z, b = z >> 4, h = z & 15;
    int s0 = blockIdx.x * 32, d0 = blockIdx.y * 32;
    int tx = threadIdx.x, ty = threadIdx.y;
    #pragma unroll
    for (int i = 0; i < 32; i += 8)
        t[ty + i][tx] = g_vf[(size_t)(b * SSx + s0 + ty + i) * UPx + h * VHDx + d0 + tx];
    __syncthreads();
    #pragma unroll
    for (int i = 0; i < 32; i += 8)
        g_vtsh[(size_t)z * (VHDx * SSx) + (size_t)(d0 + ty + i) * SSx + s0 + tx] =
            __half_as_ushort(__float2half_rn(t[tx][ty + i]));
}
__global__ void __launch_bounds__(128) k_softmax() {
    size_t row = blockIdx.x;
    const uint16_t* p = g_sch + row * SSx;
    int t = threadIdx.x;
    uint2 raw = ((const uint2*)p)[t];
    __half2 h01 = *(__half2*)&raw.x, h23 = *(__half2*)&raw.y;
    float4 v = make_float4(__low2float(h01), __high2float(h01),
                           __low2float(h23), __high2float(h23));
    float m = fmaxf(fmaxf(v.x, v.y), fmaxf(v.z, v.w));
    #pragma unroll
    for (int o = 16; o; o >>= 1) m = fmaxf(m, __shfl_xor_sync(0xffffffffu, m, o));
    __shared__ float rm[4], rs[4];
    if ((t & 31) == 0) rm[t >> 5] = m;
    __syncthreads();
    m = fmaxf(fmaxf(rm[0], rm[1]), fmaxf(rm[2], rm[3]));
    v.x = __expf(v.x - m); v.y = __expf(v.y - m);
    v.z = __expf(v.z - m); v.w = __expf(v.w - m);
    float s = v.x + v.y + v.z + v.w;
    #pragma unroll
    for (int o = 16; o; o >>= 1) s += __shfl_xor_sync(0xffffffffu, s, o);
    if ((t & 31) == 0) rs[t >> 5] = s;
    __syncthreads();
    s = rs[0] + rs[1] + rs[2] + rs[3];
    float inv = 1.f / s;
    *(uint2*)(g_psh + row * SSx + t * 4) =
        make_uint2(h2pack(v.x * inv, v.y * inv), h2pack(v.z * inv, v.w * inv));
}

extern "C" void kernel_launch(void* const* d_in, const int* in_sizes, int n_in,
                              void* d_out, int out_size)
{
    const float* X    = (const float*)d_in[0];
    const float* Wdq  = (const float*)d_in[1];
    const float* bdq  = (const float*)d_in[2];
    const float* Wdkv = (const float*)d_in[3];
    const float* bdkv = (const float*)d_in[4];
    const float* Wuq  = (const float*)d_in[5];
    const float* buq  = (const float*)d_in[6];
    const float* Wuk  = (const float*)d_in[7];
    const float* buk  = (const float*)d_in[8];
    const float* Wuv  = (const float*)d_in[9];
    const float* buv  = (const float*)d_in[10];
    const float* Wqr  = (const float*)d_in[11];
    const float* bqr  = (const float*)d_in[12];
    const float* Wkr  = (const float*)d_in[13];
    const float* bkr  = (const float*)d_in[14];
    const float* Wfc  = (const float*)d_in[15];
    const float* bfc  = (const float*)d_in[16];
    float* out = (float*)d_out;

    cudaFuncSetAttribute(k_gemm, cudaFuncAttributeMaxDynamicSharedMemorySize, SMEMB);
    cudaFuncSetAttribute(k_gemm_qk, cudaFuncAttributeMaxDynamicSharedMemorySize, SMEMB);

    #define SYM(v, g) void* v; cudaGetSymbolAddress(&v, g)
    SYM(p_xh, g_xh);
    SYM(p_wdth, g_wdth); SYM(p_bd, g_bd);
    SYM(p_wqth, g_wqth); SYM(p_wkvth, g_wkvth);
    SYM(p_bq, g_bq); SYM(p_bkv, g_bkv);
    SYM(p_wfcth, g_wfcth);
    SYM(p_d0h, g_d0h);
    SYM(p_quh, g_quh);
    SYM(p_kch, g_kch); SYM(p_vf, g_vf);
    SYM(p_psh, g_psh);
    SYM(p_vtsh, g_vtsh);
    SYM(p_ofsh, g_ofsh);
    #undef SYM

    dim3 tb(32, 8);
    k_table<<<SSx, 256>>>();
    k_half_x<<<(MROWS * DDx / 2) / 256, 256>>>(X, (uint16_t*)p_xh, MROWS * DDx / 2);
    k_trsp<<<dim3(16, 64), tb>>>(Wdq,  (uint16_t*)p_wdth, 2048, 512);
    k_trsp<<<dim3(16, 64), tb>>>(Wdkv, (uint16_t*)p_wdth + (size_t)512 * 2048, 2048, 512);
    k_trsp<<<dim3(16, 64), tb>>>(Wkr,  (uint16_t*)p_wdth + (size_t)1024 * 2048, 2048, 512);
    k_trsp<<<dim3(64, 16), tb>>>(Wuq, (uint16_t*)p_wqth, 512, 2048);
    k_trsp<<<dim3(256, 16), tb>>>(Wqr, (uint16_t*)p_wqth + (size_t)UPx * 512, 512, 8192);
    k_trsp<<<dim3(64, 16), tb>>>(Wuk, (uint16_t*)p_wkvth, 512, 2048);
    k_trsp<<<dim3(64, 16), tb>>>(Wuv, (uint16_t*)p_wkvth + (size_t)UPx * 512, 512, 2048);
    k_trsp<<<dim3(64, 64), tb>>>(Wfc, (uint16_t*)p_wfcth, 2048, 2048);
    k_cat3<<<(NDOWN + 255) / 256, 256>>>((float*)p_bd, bdq, bdkv, bkr, 512, 512, 512);
    k_cat2<<<(NQ + 255) / 256, 256>>>((float*)p_bq, buq, bqr, UPx, RRx * HHx);
    k_cat2<<<(NKV + 255) / 256, 256>>>((float*)p_bkv, buk, buv, UPx, UPx);

    // fused down-proj + k_r rope: M=4096, N=1536, K=2048
    k_gemm<<<dim3(12, 32, 1), 256, SMEMB>>>(
        (uint16_t*)p_xh, DDx, 0,
        (uint16_t*)p_wdth, DDx, 0,
        nullptr, (uint16_t*)p_d0h, NDOWN, 0, 0,
        (float*)p_bd, 1.f, DDx, 4);

    // merged q-side up-proj (rope fused): M=4096, N=10240, K=512
    k_gemm<<<dim3(80, 32, 1), 256, SMEMB>>>(
        (uint16_t*)p_d0h, NDOWN, 0,
        (uint16_t*)p_wqth, DWN, 0,
        nullptr, (uint16_t*)p_quh, NQ, 0, 0,
        (float*)p_bq, 1.f, DWN, 1);
    // merged kv-side up-proj: K fp16 + V fp32: M=4096, N=4096, K=512
    k_gemm<<<dim3(32, 32, 1), 256, SMEMB>>>(
        (uint16_t*)p_d0h + 512, NDOWN, 0,
        (uint16_t*)p_wkvth, DWN, 0,
        (float*)p_vf, (uint16_t*)p_kch, 2048, 0, 0,
        (float*)p_bkv, 1.f, DWN, 2);

    k_vt<<<dim3(16, 4, ZBx), tb>>>();

    // scores: per z M=512, N=512, K=640 -> fp16
    k_gemm_qk<<<dim3(4, 4, ZBx), 256, SMEMB>>>();

    k_softmax<<<ZBx * SSx, 128>>>();

    // PV: per z M=512, N=128, K=512 -> fp16 O, z-scatter
    k_gemm<<<dim3(1, 4, ZBx), 256, SMEMB>>>(
        (uint16_t*)p_psh, SSx, (long long)SSx * SSx,
        (uint16_t*)p_vtsh, SSx, (long long)VHDx * SSx,
        nullptr, (uint16_t*)p_ofsh, UPx,
        (long long)SSx * UPx, (long long)VHDx,
        nullptr, 1.f, SSx, 3);

    // final: M=4096, N=2048, K=2048 -> out fp32
    k_gemm<<<dim3(16, 32, 1), 256, SMEMB>>>(
        (uint16_t*)p_ofsh, UPx, 0,
        (uint16_t*)p_wfcth, DDx, 0,
        out, nullptr, DDx, 0, 0, bfc, 1.f, DDx, 0);
}

// round 17
// speedup vs baseline: 1.7035x; 1.1363x over previous
#include <cuda_runtime.h>
#include <cuda_fp16.h>
#include <cstdint>
#include <math.h>

#define BBx   8
#define SSx   512
#define DDx   2048
#define HHx   16
#define DWN   512
#define UPx   2048
#define RRx   512
#define VHDx  128
#define MROWS (BBx*SSx)
#define ZBx   (BBx*HHx)
#define QKD   (VHDx+RRx)
#define NDOWN (DWN*3)
#define NQ    (UPx + RRx*HHx)     // 10240
#define NKV   (UPx + UPx)         // 4096
#define INV_SCALE 0.0294627825494394758f

__device__ uint16_t g_xh  [(size_t)MROWS*DDx];
__device__ uint16_t g_wdth[(size_t)NDOWN*DDx];
__device__ float    g_bd  [NDOWN];
__device__ uint16_t g_wqth[(size_t)NQ*DWN];
__device__ uint16_t g_wkvth[(size_t)NKV*DWN];
__device__ float    g_bq  [NQ];
__device__ float    g_bkv [NKV];
__device__ uint16_t g_wfcth[(size_t)DDx*DDx];
__device__ uint16_t g_d0h [(size_t)MROWS*NDOWN];
__device__ uint16_t g_quh [(size_t)MROWS*NQ];
__device__ uint16_t g_kch [(size_t)MROWS*UPx];
__device__ uint16_t g_vfh [(size_t)MROWS*UPx];      // V fp16 (pre-transpose)
__device__ uint16_t g_krh [(size_t)MROWS*RRx];
__device__ uint16_t g_sch [(size_t)ZBx*SSx*SSx];
__device__ uint16_t g_psh [(size_t)ZBx*SSx*SSx];
__device__ uint16_t g_vtsh[(size_t)ZBx*VHDx*SSx];
__device__ uint16_t g_ofsh[(size_t)MROWS*UPx];
__device__ float    g_sin [SSx*(RRx/2)];
__device__ float    g_cos [SSx*(RRx/2)];

__device__ __forceinline__ uint32_t smem_u32(const void* p) {
    uint32_t a;
    asm("{ .reg .u64 t; cvta.to.shared.u64 t, %1; cvt.u32.u64 %0, t; }" : "=r"(a) : "l"(p));
    return a;
}
__device__ __forceinline__ uint32_t h2pack(float a, float b) {
    __half2 h = __floats2half2_rn(a, b);
    return *(uint32_t*)&h;
}
__device__ __forceinline__ void ldm4(uint32_t* r, uint32_t addr) {
    asm volatile("ldmatrix.sync.aligned.m8n8.x4.shared.b16 {%0,%1,%2,%3}, [%4];"
        : "=r"(r[0]), "=r"(r[1]), "=r"(r[2]), "=r"(r[3]) : "r"(addr));
}
__device__ __forceinline__ void mma16816(float* c, const uint32_t* a, const uint32_t* b) {
    asm volatile("mma.sync.aligned.m16n8k16.row.col.f32.f16.f16.f32 "
        "{%0,%1,%2,%3}, {%4,%5,%6,%7}, {%8,%9}, {%0,%1,%2,%3};"
        : "+f"(c[0]), "+f"(c[1]), "+f"(c[2]), "+f"(c[3])
        : "r"(a[0]), "r"(a[1]), "r"(a[2]), "r"(a[3]), "r"(b[0]), "r"(b[1]));
}
#define CP16(dst, src) \
    asm volatile("cp.async.cg.shared.global [%0], [%1], 16;" :: "r"(dst), "l"(src))
#define CP_COMMIT() asm volatile("cp.async.commit_group;" ::: "memory")
#define CP_WAIT0()  asm volatile("cp.async.wait_group 0;" ::: "memory")

// BK=64: plane = 128 rows x 144B pitch (128B payload = 64 fp16)
#define PITCH  144
#define PLA_L  (128*PITCH)
#define STG_L  (2*PLA_L)          // 36864 per stage
#define SMEMB  (2*STG_L)          // 73728 -> 2 CTAs/SM (147KB)

// ------------------ generic GEMM: C = scale*(A @ B^T) + bias --------------------
// emode 0: fp32 Cf; 1: q-up rope fp16; 2: kv-up (K->Csh fp16, V->g_vfh fp16);
// emode 3: fp16 z-scatter; 4: down-proj (cq|ckv fp16, kr roped -> g_krh)
__global__ void __launch_bounds__(256, 2) k_gemm(
    const uint16_t* __restrict__ Ah, int lda, long long aB,
    const uint16_t* __restrict__ Bh, int ldb, long long bB,
    float* Cf, uint16_t* Csh, int ldc, long long cO, long long cI,
    const float* __restrict__ bias, float scale, int K, int emode)
{
    extern __shared__ __align__(16) char smem[];
    const uint32_t sb = smem_u32(smem);
    const int tid = threadIdx.x, lane = tid & 31, wid = tid >> 5;
    const int wm = wid >> 1, wn = wid & 1;     // 4m x 2n
    const int z = blockIdx.z, bm = blockIdx.y, bn = blockIdx.x;

    const uint16_t* pb0 = Ah + (size_t)z * aB + (size_t)bm * 128 * lda;
    const uint16_t* pb1 = Bh + (size_t)z * bB + (size_t)bn * 128 * ldb;
    const int nCh = K / 64;

    auto issue = [&](int c) {
        if (c < nCh) {
            const int kc = c * 64;
            const uint32_t sdst = sb + (c & 1) * STG_L;
            const int row = (tid >> 3);           // 0..31
            const int col16 = (tid & 7);          // 0..7 (16B units)
            #pragma unroll
            for (int p = 0; p < 8; p++) {
                const int pl = p >> 2;
                const int r = (p & 3) * 32 + row;
                const uint16_t* src = pl ? pb1 : pb0;
                const int ld = pl ? ldb : lda;
                CP16(sdst + pl * PLA_L + r * PITCH + col16 * 16,
                     src + (size_t)r * ld + kc + col16 * 8);
            }
            CP_COMMIT();
        }
    };

    float acc[2][8][4];
    #pragma unroll
    for (int i = 0; i < 2; i++)
        #pragma unroll
        for (int j = 0; j < 8; j++)
            #pragma unroll
            for (int r = 0; r < 4; r++) acc[i][j][r] = 0.f;

    issue(0);

    for (int c = 0; c < nCh; c++) {
        CP_WAIT0();
        __syncthreads();
        issue(c + 1);

        const uint32_t sbuf = sb + (c & 1) * STG_L;
        #pragma unroll
        for (int k16 = 0; k16 < 4; k16++) {
            uint32_t af[2][4];
            uint32_t abase = sbuf + (wm * 32 + (lane & 15)) * PITCH
                           + (k16 * 16 + (lane >> 4) * 8) * 2;
            #pragma unroll
            for (int mt = 0; mt < 2; mt++)
                ldm4(af[mt], abase + mt * 16 * PITCH);
            uint32_t bbase = sbuf + PLA_L
                + (wn * 64 + (lane & 7) + ((lane >> 4) << 3)) * PITCH
                + (k16 * 16 + ((lane >> 3) & 1) * 8) * 2;
            #pragma unroll
            for (int nb = 0; nb < 4; nb++) {
                uint32_t bh[4];
                ldm4(bh, bbase + nb * 16 * PITCH);
                #pragma unroll
                for (int hf = 0; hf < 2; hf++) {
                    const int nt = nb * 2 + hf;
                    #pragma unroll
                    for (int mt = 0; mt < 2; mt++)
                        mma16816(acc[mt][nt], af[mt], &bh[2 * hf]);
                }
            }
        }
    }

    const long long coff = (long long)(z >> 4) * cO + (long long)(z & 15) * cI;
    #pragma unroll
    for (int nt = 0; nt < 8; nt++) {
        const int gc = bn * 128 + wn * 64 + nt * 8 + (lane & 3) * 2;
        float2 bv = make_float2(0.f, 0.f);
        if (bias) bv = *(const float2*)(bias + gc);
        #pragma unroll
        for (int mt = 0; mt < 2; mt++) {
            const int r0 = bm * 128 + wm * 32 + mt * 16 + (lane >> 2);
            #pragma unroll
            for (int half = 0; half < 2; half++) {
                const int grow = r0 + half * 8;
                float v0 = acc[mt][nt][2 * half + 0] * scale + bv.x;
                float v1 = acc[mt][nt][2 * half + 1] * scale + bv.y;
                if (emode == 0) {
                    *(float2*)(Cf + coff + (long long)grow * ldc + gc) =
                        make_float2(v0, v1);
                } else if (emode == 1) {
                    if (gc >= 2048) {
                        const int s = grow & (SSx - 1);
                        const int ii = s * 256 + (((gc - 2048) & (RRx - 1)) >> 1);
                        float sn = g_sin[ii], cs = g_cos[ii];
                        float o0 = v0 * cs - v1 * sn;
                        float o1 = v1 * cs + v0 * sn;
                        v0 = o0; v1 = o1;
                    }
                    *(uint32_t*)(Csh + (long long)grow * ldc + gc) = h2pack(v0, v1);
                } else if (emode == 2) {
                    if (gc < 2048)
                        *(uint32_t*)(Csh + (long long)grow * 2048 + gc) = h2pack(v0, v1);
                    else
                        *(uint32_t*)(g_vfh + (long long)grow * 2048 + gc - 2048) =
                            h2pack(v0, v1);
                } else if (emode == 3) {
                    *(uint32_t*)(Csh + coff + (long long)grow * ldc + gc) =
                        h2pack(v0, v1);
                } else {   // emode 4
                    if (gc < 1024) {
                        *(uint32_t*)(Csh + (long long)grow * ldc + gc) = h2pack(v0, v1);
                    } else {
                        const int s = grow & (SSx - 1);
                        const int i2 = gc - 1024;
                        const int ii = s * 256 + (i2 >> 1);
                        float sn = g_sin[ii], cs = g_cos[ii];
                        *(uint32_t*)(g_krh + (long long)grow * RRx + i2) =
                            h2pack(v0 * cs - v1 * sn, v1 * cs + v0 * sn);
                    }
                }
            }
        }
    }
}

// ---------- scores GEMM, piecewise q/k addressing, fp16 output, BK=64 -----------
__global__ void __launch_bounds__(256, 2) k_gemm_qk()
{
    extern __shared__ __align__(16) char smem[];
    const uint32_t sb = smem_u32(smem);
    const int tid = threadIdx.x, lane = tid & 31, wid = tid >> 5;
    const int wm = wid >> 1, wn = wid & 1;
    const int z = blockIdx.z, bm = blockIdx.y, bn = blockIdx.x;
    const int b = z >> 4, h = z & 15;
    const long long gRow0 = (long long)b * SSx + bm * 128;
    const long long kRow0 = (long long)b * SSx + bn * 128;
    const int nCh = QKD / 64;    // 10: chunks 0-1 content, 2-9 rope

    auto issue = [&](int c) {
        if (c < nCh) {
            const uint32_t sdst = sb + (c & 1) * STG_L;
            const int row = (tid >> 3);
            const int col16 = (tid & 7);
            const int colA = (c < 2) ? (h * VHDx + c * 64)
                                     : (2048 + h * RRx + (c - 2) * 64);
            #pragma unroll
            for (int p = 0; p < 8; p++) {
                const int pl = p >> 2;
                const int r = (p & 3) * 32 + row;
                uint32_t dst = sdst + pl * PLA_L + r * PITCH + col16 * 16;
                if (pl == 0) {
                    CP16(dst, g_quh + (gRow0 + r) * NQ + colA + col16 * 8);
                } else {
                    if (c < 2)
                        CP16(dst, g_kch + (kRow0 + r) * UPx + h * VHDx + c * 64 + col16 * 8);
                    else
                        CP16(dst, g_krh + (kRow0 + r) * RRx + (c - 2) * 64 + col16 * 8);
                }
            }
            CP_COMMIT();
        }
    };

    float acc[2][8][4];
    #pragma unroll
    for (int i = 0; i < 2; i++)
        #pragma unroll
        for (int j = 0; j < 8; j++)
            #pragma unroll
            for (int r = 0; r < 4; r++) acc[i][j][r] = 0.f;

    issue(0);

    for (int c = 0; c < nCh; c++) {
        CP_WAIT0();
        __syncthreads();
        issue(c + 1);

        const uint32_t sbuf = sb + (c & 1) * STG_L;
        #pragma unroll
        for (int k16 = 0; k16 < 4; k16++) {
            uint32_t af[2][4];
            uint32_t abase = sbuf + (wm * 32 + (lane & 15)) * PITCH
                           + (k16 * 16 + (lane >> 4) * 8) * 2;
            #pragma unroll
            for (int mt = 0; mt < 2; mt++)
                ldm4(af[mt], abase + mt * 16 * PITCH);
            uint32_t bbase = sbuf + PLA_L
                + (wn * 64 + (lane & 7) + ((lane >> 4) << 3)) * PITCH
                + (k16 * 16 + ((lane >> 3) & 1) * 8) * 2;
            #pragma unroll
            for (int nb = 0; nb < 4; nb++) {
                uint32_t bh[4];
                ldm4(bh, bbase + nb * 16 * PITCH);
                #pragma unroll
                for (int hf = 0; hf < 2; hf++) {
                    const int nt = nb * 2 + hf;
                    #pragma unroll
                    for (int mt = 0; mt < 2; mt++)
                        mma16816(acc[mt][nt], af[mt], &bh[2 * hf]);
                }
            }
        }
    }

    uint16_t* C = g_sch + (size_t)z * SSx * SSx;
    #pragma unroll
    for (int nt = 0; nt < 8; nt++) {
        const int gc = bn * 128 + wn * 64 + nt * 8 + (lane & 3) * 2;
        #pragma unroll
        for (int mt = 0; mt < 2; mt++) {
            const int r0 = bm * 128 + wm * 32 + mt * 16 + (lane >> 2);
            #pragma unroll
            for (int half = 0; half < 2; half++) {
                const long long gp = (long long)(r0 + half * 8) * SSx + gc;
                *(uint32_t*)(C + gp) = h2pack(
                    acc[mt][nt][2 * half + 0] * INV_SCALE,
                    acc[mt][nt][2 * half + 1] * INV_SCALE);
            }
        }
    }
}

__global__ void k_half_x(const float* __restrict__ s, uint16_t* __restrict__ dh, int n2) {
    int i = blockIdx.x * 256 + threadIdx.x;
    if (i < n2) {
        float2 v = *(const float2*)(s + 2 * i);
        *(uint32_t*)(dh + 2 * i) = h2pack(v.x, v.y);
    }
}
__global__ void k_trsp(const float* __restrict__ W, uint16_t* __restrict__ Wth,
                       int Kd, int Nd) {
    __shared__ float t[32][33];
    int n0 = blockIdx.x * 32, k0 = blockIdx.y * 32;
    int tx = threadIdx.x, ty = threadIdx.y;
    #pragma unroll
    for (int i = 0; i < 32; i += 8)
        t[ty + i][tx] = W[(size_t)(k0 + ty + i) * Nd + n0 + tx];
    __syncthreads();
    #pragma unroll
    for (int i = 0; i < 32; i += 8)
        Wth[(size_t)(n0 + ty + i) * Kd + k0 + tx] =
            __half_as_ushort(__float2half_rn(t[tx][ty + i]));
}
__global__ void k_cat3(float* dst, const float* a, const float* b, const float* c,
                       int na, int nb, int nc) {
    int i = blockIdx.x * 256 + threadIdx.x;
    if (i < na) dst[i] = a[i];
    else if (i < na + nb) dst[i] = b[i - na];
    else if (i < na + nb + nc) dst[i] = c[i - na - nb];
}
__global__ void k_cat2(float* dst, const float* a, const float* b, int na, int nb) {
    int i = blockIdx.x * 256 + threadIdx.x;
    if (i < na) dst[i] = a[i];
    else if (i < na + nb) dst[i] = b[i - na];
}
__global__ void k_table() {
    int idx = blockIdx.x * 256 + threadIdx.x;
    int s = idx >> 8, i = idx & 255;
    float dv = expf((float)(2 * i) * (-9.210340371976184f / (float)RRx));
    float sn, cs; sincosf((float)s * dv, &sn, &cs);
    g_sin[idx] = sn; g_cos[idx] = cs;
}
__global__ void k_vt() {   // fp16 in, fp16 out transpose
    __shared__ uint16_t t[32][34];
    int z = blockIdx.z, b = z >> 4, h = z & 15;
    int s0 = blockIdx.x * 32, d0 = blockIdx.y * 32;
    int tx = threadIdx.x, ty = threadIdx.y;
    #pragma unroll
    for (int i = 0; i < 32; i += 8)
        t[ty + i][tx] = g_vfh[(size_t)(b * SSx + s0 + ty + i) * UPx + h * VHDx + d0 + tx];
    __syncthreads();
    #pragma unroll
    for (int i = 0; i < 32; i += 8)
        g_vtsh[(size_t)z * (VHDx * SSx) + (size_t)(d0 + ty + i) * SSx + s0 + tx] =
            t[tx][ty + i];
}
__global__ void __launch_bounds__(128) k_softmax() {
    size_t row = blockIdx.x;
    const uint16_t* p = g_sch + row * SSx;
    int t = threadIdx.x;
    uint2 raw = ((const uint2*)p)[t];
    __half2 h01 = *(__half2*)&raw.x, h23 = *(__half2*)&raw.y;
    float4 v = make_float4(__low2float(h01), __high2float(h01),
                           __low2float(h23), __high2float(h23));
    float m = fmaxf(fmaxf(v.x, v.y), fmaxf(v.z, v.w));
    #pragma unroll
    for (int o = 16; o; o >>= 1) m = fmaxf(m, __shfl_xor_sync(0xffffffffu, m, o));
    __shared__ float rm[4], rs[4];
    if ((t & 31) == 0) rm[t >> 5] = m;
    __syncthreads();
    m = fmaxf(fmaxf(rm[0], rm[1]), fmaxf(rm[2], rm[3]));
    v.x = __expf(v.x - m); v.y = __expf(v.y - m);
    v.z = __expf(v.z - m); v.w = __expf(v.w - m);
    float s = v.x + v.y + v.z + v.w;
    #pragma unroll
    for (int o = 16; o; o >>= 1) s += __shfl_xor_sync(0xffffffffu, s, o);
    if ((t & 31) == 0) rs[t >> 5] = s;
    __syncthreads();
    s = rs[0] + rs[1] + rs[2] + rs[3];
    float inv = 1.f / s;
    *(uint2*)(g_psh + row * SSx + t * 4) =
        make_uint2(h2pack(v.x * inv, v.y * inv), h2pack(v.z * inv, v.w * inv));
}

extern "C" void kernel_launch(void* const* d_in, const int* in_sizes, int n_in,
                              void* d_out, int out_size)
{
    const float* X    = (const float*)d_in[0];
    const float* Wdq  = (const float*)d_in[1];
    const float* bdq  = (const float*)d_in[2];
    const float* Wdkv = (const float*)d_in[3];
    const float* bdkv = (const float*)d_in[4];
    const float* Wuq  = (const float*)d_in[5];
    const float* buq  = (const float*)d_in[6];
    const float* Wuk  = (const float*)d_in[7];
    const float* buk  = (const float*)d_in[8];
    const float* Wuv  = (const float*)d_in[9];
    const float* buv  = (const float*)d_in[10];
    const float* Wqr  = (const float*)d_in[11];
    const float* bqr  = (const float*)d_in[12];
    const float* Wkr  = (const float*)d_in[13];
    const float* bkr  = (const float*)d_in[14];
    const float* Wfc  = (const float*)d_in[15];
    const float* bfc  = (const float*)d_in[16];
    float* out = (float*)d_out;

    cudaFuncSetAttribute(k_gemm, cudaFuncAttributeMaxDynamicSharedMemorySize, SMEMB);
    cudaFuncSetAttribute(k_gemm_qk, cudaFuncAttributeMaxDynamicSharedMemorySize, SMEMB);

    #define SYM(v, g) void* v; cudaGetSymbolAddress(&v, g)
    SYM(p_xh, g_xh);
    SYM(p_wdth, g_wdth); SYM(p_bd, g_bd);
    SYM(p_wqth, g_wqth); SYM(p_wkvth, g_wkvth);
    SYM(p_bq, g_bq); SYM(p_bkv, g_bkv);
    SYM(p_wfcth, g_wfcth);
    SYM(p_d0h, g_d0h);
    SYM(p_quh, g_quh);
    SYM(p_kch, g_kch);
    SYM(p_psh, g_psh);
    SYM(p_vtsh, g_vtsh);
    SYM(p_ofsh, g_ofsh);
    #undef SYM

    dim3 tb(32, 8);
    k_table<<<SSx, 256>>>();
    k_half_x<<<(MROWS * DDx / 2) / 256, 256>>>(X, (uint16_t*)p_xh, MROWS * DDx / 2);
    k_trsp<<<dim3(16, 64), tb>>>(Wdq,  (uint16_t*)p_wdth, 2048, 512);
    k_trsp<<<dim3(16, 64), tb>>>(Wdkv, (uint16_t*)p_wdth + (size_t)512 * 2048, 2048, 512);
    k_trsp<<<dim3(16, 64), tb>>>(Wkr,  (uint16_t*)p_wdth + (size_t)1024 * 2048, 2048, 512);
    k_trsp<<<dim3(64, 16), tb>>>(Wuq, (uint16_t*)p_wqth, 512, 2048);
    k_trsp<<<dim3(256, 16), tb>>>(Wqr, (uint16_t*)p_wqth + (size_t)UPx * 512, 512, 8192);
    k_trsp<<<dim3(64, 16), tb>>>(Wuk, (uint16_t*)p_wkvth, 512, 2048);
    k_trsp<<<dim3(64, 16), tb>>>(Wuv, (uint16_t*)p_wkvth + (size_t)UPx * 512, 512, 2048);
    k_trsp<<<dim3(64, 64), tb>>>(Wfc, (uint16_t*)p_wfcth, 2048, 2048);
    k_cat3<<<(NDOWN + 255) / 256, 256>>>((float*)p_bd, bdq, bdkv, bkr, 512, 512, 512);
    k_cat2<<<(NQ + 255) / 256, 256>>>((float*)p_bq, buq, bqr, UPx, RRx * HHx);
    k_cat2<<<(NKV + 255) / 256, 256>>>((float*)p_bkv, buk, buv, UPx, UPx);

    // fused down-proj + k_r rope: M=4096, N=1536, K=2048
    k_gemm<<<dim3(12, 32, 1), 256, SMEMB>>>(
        (uint16_t*)p_xh, DDx, 0,
        (uint16_t*)p_wdth, DDx, 0,
        nullptr, (uint16_t*)p_d0h, NDOWN, 0, 0,
        (float*)p_bd, 1.f, DDx, 4);

    // merged q-side up-proj (rope fused): M=4096, N=10240, K=512
    k_gemm<<<dim3(80, 32, 1), 256, SMEMB>>>(
        (uint16_t*)p_d0h, NDOWN, 0,
        (uint16_t*)p_wqth, DWN, 0,
        nullptr, (uint16_t*)p_quh, NQ, 0, 0,
        (float*)p_bq, 1.f, DWN, 1);
    // merged kv-side up-proj: K fp16 + V fp16: M=4096, N=4096, K=512
    k_gemm<<<dim3(32, 32, 1), 256, SMEMB>>>(
        (uint16_t*)p_d0h + 512, NDOWN, 0,
        (uint16_t*)p_wkvth, DWN, 0,
        nullptr, (uint16_t*)p_kch, 2048, 0, 0,
        (float*)p_bkv, 1.f, DWN, 2);

    k_vt<<<dim3(16, 4, ZBx), tb>>>();

    // scores: per z M=512, N=512, K=640 -> fp16
    k_gemm_qk<<<dim3(4, 4, ZBx), 256, SMEMB>>>();

    k_softmax<<<ZBx * SSx, 128>>>();

    // PV: per z M=512, N=128, K=512 -> fp16 O, z-scatter
    k_gemm<<<dim3(1, 4, ZBx), 256, SMEMB>>>(
        (uint16_t*)p_psh, SSx, (long long)SSx * SSx,
        (uint16_t*)p_vtsh, SSx, (long long)VHDx * SSx,
        nullptr, (uint16_t*)p_ofsh, UPx,
        (long long)SSx * UPx, (long long)VHDx,
        nullptr, 1.f, SSx, 3);

    // final: M=4096, N=2048, K=2048 -> out fp32
    k_gemm<<<dim3(16, 32, 1), 256, SMEMB>>>(
        (uint16_t*)p_ofsh, UPx, 0,
        (uint16_t*)p_wfcth, DDx, 0,
        out, nullptr, DDx, 0, 0, bfc, 1.f, DDx, 0);
}